// round 13
// baseline (speedup 1.0000x reference)
#include <cuda_runtime.h>
#include <cuda_fp16.h>
#include <mma.h>
#include <math.h>

using namespace nvcuda;

#define Bsz 4
#define Cc 512
#define MID 256
#define CMn 76
#define Hh 128
#define Ww 128
#define HW 16384
#define Pp 1024
#define Np 16

// ---------------- static scratch ----------------
__device__ float  g_pool[Bsz * CMn * Np];
__device__ __half g_smxh[(size_t)64 * 80 * 1024];       // softmax(sim), padded 80 rows
__device__ __half g_localh[(size_t)64 * 80 * 512];      // local (conf folded), padded
__device__ __half g_kkh[(size_t)64 * 76 * 256];         // k proj (half)
__device__ __half g_vvh[76 * 256];                      // v proj (half)
__device__ __half g_oh[(size_t)64 * 1024 * 256];        // attn out HALF, patch-major
__device__ __half g_xh[(size_t)Bsz * Cc * HW];          // x as half
__device__ __half g_Wq_h[Cc * MID];
__device__ __half g_Wk_h[Cc * MID];
__device__ __half g_Wc_h[MID * Cc];
__device__ float  g_qbias[16 * MID];
__device__ __half g_w2[(size_t)64 * 512 * 80];          // W2 = Wq @ K^T per bn [ch][cm]
__device__ float  g_b2[64 * 16 * 80];                   // b2 = bq @ K^T, replicated 16 rows

// ---------------- cp.async helpers ----------------
__device__ __forceinline__ void cp16(void* dst, const void* src) {
    unsigned d = (unsigned)__cvta_generic_to_shared(dst);
    asm volatile("cp.async.ca.shared.global [%0], [%1], 16;\n" :: "r"(d), "l"(src));
}
__device__ __forceinline__ void cp_commit() { asm volatile("cp.async.commit_group;\n"); }
template <int N>
__device__ __forceinline__ void cp_wait() { asm volatile("cp.async.wait_group %0;\n" :: "n"(N)); }

// convert a 16x16 fp32 warp scratch tile (ld=20) to half and write out (ldg mult of 8).
__device__ __forceinline__ void scr_to_half(const float* scr, __half* gdst, int ldg, int lane) {
    int rr = lane >> 1, c8 = (lane & 1) * 8;
    const float* s = scr + rr * 20 + c8;
    __half2 h0 = __floats2half2_rn(s[0], s[1]);
    __half2 h1 = __floats2half2_rn(s[2], s[3]);
    __half2 h2 = __floats2half2_rn(s[4], s[5]);
    __half2 h3 = __floats2half2_rn(s[6], s[7]);
    uint4 o;
    o.x = *(unsigned*)&h0; o.y = *(unsigned*)&h1;
    o.z = *(unsigned*)&h2; o.w = *(unsigned*)&h3;
    *(uint4*)(gdst + (size_t)rr * ldg + c8) = o;
}

// ---------------- 0. merged misc: setup + x->half + pool/softmax + v -------
__global__ void k_misc(const float* __restrict__ x, const float* __restrict__ sim,
                       const float* __restrict__ gcc,
                       const float* __restrict__ Wq, const float* __restrict__ Wk,
                       const float* __restrict__ Wc, const float* __restrict__ bq,
                       const float* __restrict__ Wv, const float* __restrict__ bv,
                       float* __restrict__ out_tail) {
    __shared__ float red[256];
    __shared__ float sg[512];
    int blk = blockIdx.x;
    int t = threadIdx.x;

    if (blk < 256) {
        int g = blk * 256 + t;
        int stride = 256 * 256;
        for (int i = g; i < Cc * MID; i += stride) {
            g_Wq_h[i] = __float2half(Wq[i]);
            g_Wk_h[i] = __float2half(Wk[i]);
            g_Wc_h[i] = __float2half(Wc[i]);
        }
        for (int i = g; i < 16 * MID; i += stride) g_qbias[i] = bq[i & (MID - 1)];
        for (int i = g; i < 64 * 4 * 1024; i += stride) {
            int bn = i >> 12, rem = i & 4095;
            g_smxh[((size_t)bn * 80 + 76) * 1024 + rem] = __float2half(0.f);
        }
        for (int i = g; i < 64 * 4 * 512; i += stride) {
            int bn = i >> 11, rem = i & 2047;
            g_localh[((size_t)bn * 80 + 76) * 512 + rem] = __float2half(0.f);
        }
    } else if (blk < 2304) {
        size_t n8 = (size_t)Bsz * Cc * HW / 8;
        size_t g = (size_t)(blk - 256) * 256 + t;
        size_t stride = (size_t)2048 * 256;
        for (; g < n8; g += stride) {
            const float4* s = (const float4*)x + g * 2;
            float4 a = s[0], b = s[1];
            __half2 h0 = __floats2half2_rn(a.x, a.y);
            __half2 h1 = __floats2half2_rn(a.z, a.w);
            __half2 h2 = __floats2half2_rn(b.x, b.y);
            __half2 h3 = __floats2half2_rn(b.z, b.w);
            uint4 o;
            o.x = *(unsigned*)&h0; o.y = *(unsigned*)&h1;
            o.z = *(unsigned*)&h2; o.w = *(unsigned*)&h3;
            ((uint4*)g_xh)[g] = o;
        }
    } else if (blk < 7168) {
        int id = blk - 2304;
        int cm = id % CMn;
        int bn = id / CMn;
        int n = bn & 15, b = bn >> 4;
        int i0 = (n >> 2) * 32, j0 = (n & 3) * 32;
        const float* base = sim + ((size_t)b * CMn + cm) * HW;
        float v[4];
        float mx = -1e30f, sraw = 0.f;
#pragma unroll
        for (int it = 0; it < 4; it++) {
            int p = t + it * 256;
            int pi = p >> 5, pj = p & 31;
            v[it] = base[(i0 + pi) * Ww + j0 + pj];
            mx = fmaxf(mx, v[it]);
            sraw += v[it];
        }
        red[t] = sraw; __syncthreads();
        for (int o = 128; o > 0; o >>= 1) {
            if (t < o) red[t] += red[t + o];
            __syncthreads();
        }
        if (t == 0) {
            float m = red[0] * (1.0f / 1024.0f);
            int pid = (b * CMn + cm) * 16 + n;
            g_pool[pid] = m;
            out_tail[pid] = m;
        }
        __syncthreads();
        red[t] = mx; __syncthreads();
        for (int o = 128; o > 0; o >>= 1) {
            if (t < o) red[t] = fmaxf(red[t], red[t + o]);
            __syncthreads();
        }
        float gmx = red[0]; __syncthreads();
        float s = 0.f;
#pragma unroll
        for (int it = 0; it < 4; it++) { v[it] = expf(v[it] - gmx); s += v[it]; }
        red[t] = s; __syncthreads();
        for (int o = 128; o > 0; o >>= 1) {
            if (t < o) red[t] += red[t + o];
            __syncthreads();
        }
        float inv = 1.0f / red[0];
        __half* dst = g_smxh + ((size_t)bn * 80 + cm) * Pp;
#pragma unroll
        for (int it = 0; it < 4; it++) { int p = t + it * 256; dst[p] = __float2half(v[it] * inv); }
    } else {
        int c = blk - 7168;
        for (int k = t; k < 512; k += 256) sg[k] = gcc[c * 512 + k];
        __syncthreads();
        float acc = 0.f;
        for (int k = 0; k < 512; k++) acc += sg[k] * Wv[k * MID + t];
        g_vvh[c * MID + t] = __float2half(acc + bv[t]);
    }
}

// ---------------- 3. local = smx^T @ xs * conf  (WMMA, cp.async x2) --------
__device__ __forceinline__ void local_stage(int tid, __half* Adst, __half* Bdst,
                                            const __half* Asrc, const __half* Bsrc,
                                            int it, int nBase, int baseoff) {
    for (int idx = tid; idx < 832; idx += 320) {
        if (idx < 320) {
            int row = idx >> 2, col = (idx & 3) * 8;
            cp16(Adst + row * 40 + col, Asrc + (size_t)row * 1024 + it * 32 + col);
        } else {
            int j = idx - 320;
            int row = j >> 2, col = (j & 3) * 8;
            cp16(Bdst + row * 40 + col,
                 Bsrc + (size_t)(nBase + row) * HW + baseoff + it * Ww + col);
        }
    }
    cp_commit();
}

__global__ __launch_bounds__(320, 2) void k_local_w() {
    __shared__ __align__(16) union {
        struct { __half A[2][80][40]; __half B[2][128][40]; } s;
        float C[80 * 136];
    } u;
    int bn = blockIdx.y;
    int b = bn >> 4, np = bn & 15;
    int i0 = (np >> 2) * 32, j0 = (np & 3) * 32;
    int baseoff = i0 * Ww + j0;
    int nBase = blockIdx.x * 128;
    const __half* Asrc = g_smxh + (size_t)bn * 80 * 1024;
    const __half* Bsrc = g_xh + (size_t)b * Cc * HW;
    int tid = threadIdx.x;
    int wid = tid >> 5;
    int wm = wid % 5, wn = wid / 5;

    wmma::fragment<wmma::accumulator, 16, 16, 16, float> c[4];
#pragma unroll
    for (int j = 0; j < 4; j++) wmma::fill_fragment(c[j], 0.f);

    local_stage(tid, &u.s.A[0][0][0], &u.s.B[0][0][0], Asrc, Bsrc, 0, nBase, baseoff);
    for (int it = 0; it < 32; it++) {
        if (it + 1 < 32) {
            int s2 = (it + 1) & 1;
            local_stage(tid, &u.s.A[s2][0][0], &u.s.B[s2][0][0], Asrc, Bsrc, it + 1, nBase, baseoff);
            cp_wait<1>();
        } else {
            cp_wait<0>();
        }
        __syncthreads();
        int s = it & 1;
#pragma unroll
        for (int ks = 0; ks < 32; ks += 16) {
            wmma::fragment<wmma::matrix_a, 16, 16, 16, __half, wmma::row_major> af;
            wmma::load_matrix_sync(af, &u.s.A[s][wm * 16][ks], 40);
#pragma unroll
            for (int j = 0; j < 4; j++) {
                wmma::fragment<wmma::matrix_b, 16, 16, 16, __half, wmma::col_major> bf;
                wmma::load_matrix_sync(bf, &u.s.B[s][wn * 64 + j * 16][ks], 40);
                wmma::mma_sync(c[j], af, bf, c[j]);
            }
        }
        __syncthreads();
    }
#pragma unroll
    for (int j = 0; j < 4; j++)
        wmma::store_matrix_sync(&u.C[(wm * 16) * 136 + wn * 64 + j * 16], c[j], 136,
                                wmma::mem_row_major);
    __syncthreads();
    for (int idx = tid; idx < 76 * 128; idx += 320) {
        int cc = idx >> 7, nn = idx & 127;
        float conf = g_pool[(b * CMn + cc) * 16 + np];
        g_localh[((size_t)bn * 80 + cc) * 512 + nBase + nn] =
            __float2half(u.C[cc * 136 + nn] * conf);
    }
}

// ---------------- 4. k = local @ Wk + bk (WMMA, half out) ----------------
__global__ __launch_bounds__(320, 2) void k_kproj_w(const float* __restrict__ bk) {
    __shared__ __align__(16) union {
        struct { __half A[80][40]; __half B[32][136]; } ab;
        float C[80 * 136];
    } u;
    int bn = blockIdx.y;
    int nBase = blockIdx.x * 128;
    const __half* Ap = g_localh + (size_t)bn * 80 * 512;
    int tid = threadIdx.x;
    int wid = tid >> 5;
    int wm = wid % 5, wn = wid / 5;

    wmma::fragment<wmma::accumulator, 16, 16, 16, float> c[4];
#pragma unroll
    for (int j = 0; j < 4; j++) wmma::fill_fragment(c[j], 0.f);

    for (int k0 = 0; k0 < 512; k0 += 32) {
        {
            int cc = tid >> 2;
            int h8 = (tid & 3) * 8;
            *(uint4*)&u.ab.A[cc][h8] = *(const uint4*)&Ap[(size_t)cc * 512 + k0 + h8];
        }
        for (int idx = tid; idx < 512; idx += 320) {
            int kk = idx >> 4;
            int nn = (idx & 15) * 8;
            *(uint4*)&u.ab.B[kk][nn] = *(const uint4*)&g_Wk_h[(k0 + kk) * MID + nBase + nn];
        }
        __syncthreads();
#pragma unroll
        for (int ks = 0; ks < 32; ks += 16) {
            wmma::fragment<wmma::matrix_a, 16, 16, 16, __half, wmma::row_major> af;
            wmma::load_matrix_sync(af, &u.ab.A[wm * 16][ks], 40);
#pragma unroll
            for (int j = 0; j < 4; j++) {
                wmma::fragment<wmma::matrix_b, 16, 16, 16, __half, wmma::row_major> bf;
                wmma::load_matrix_sync(bf, &u.ab.B[ks][wn * 64 + j * 16], 136);
                wmma::mma_sync(c[j], af, bf, c[j]);
            }
        }
        __syncthreads();
    }
#pragma unroll
    for (int j = 0; j < 4; j++)
        wmma::store_matrix_sync(&u.C[(wm * 16) * 136 + wn * 64 + j * 16], c[j], 136,
                                wmma::mem_row_major);
    __syncthreads();
    for (int idx = tid; idx < 76 * 128; idx += 320) {
        int cc = idx >> 7, nn = idx & 127;
        g_kkh[((size_t)bn * 76 + cc) * 256 + nBase + nn] =
            __float2half(u.C[cc * 136 + nn] + bk[nBase + nn]);
    }
}

// ---------------- 5. W2 = Wq @ K^T per bn, plus b2 = bq @ K^T --------------
// grid 64, block 256 (8 warps). smem: Ks [80][264] (42240) + union{As[128][40], scr} (10240)
#define W2_SMEM 52480

__global__ __launch_bounds__(256, 2) void k_w2(const float* __restrict__ bq) {
    extern __shared__ __align__(16) char dynw[];
    __half* Ks = (__half*)dynw;                 // [80][264]
    __half* As = (__half*)(dynw + 42240);       // [128][40]
    float* scrb = (float*)(dynw + 42240);       // 8 x [16][20]
    int bn = blockIdx.x;
    int tid = threadIdx.x;
    int lane = tid & 31;
    int wid = tid >> 5;
    const __half* ksrc = g_kkh + (size_t)bn * 76 * 256;

    // load K (80 rows, zero-padded)
    for (int idx = tid; idx < 2560; idx += 256) {
        int row = idx >> 5, c8 = (idx & 31) * 8;
        uint4 z = {0, 0, 0, 0};
        uint4 val = (row < 76) ? *(const uint4*)&ksrc[(size_t)row * 256 + c8] : z;
        *(uint4*)(Ks + row * 264 + c8) = val;
    }
    __syncthreads();

    // b2[c] = sum_mid bq[mid] * K[c][mid]; replicate 16 rows
    if (tid < 80) {
        float s = 0.f;
        for (int mid = 0; mid < 256; mid++) s += bq[mid] * __half2float(Ks[tid * 264 + mid]);
        for (int r = 0; r < 16; r++) g_b2[(size_t)bn * 1280 + r * 80 + tid] = s;
    }

    // W2[m0+row][c] = sum_mid Wq[m0+row][mid] * K[c][mid]
    for (int m0 = 0; m0 < 512; m0 += 128) {
        wmma::fragment<wmma::accumulator, 16, 16, 16, float> acc[5];
#pragma unroll
        for (int f = 0; f < 5; f++) wmma::fill_fragment(acc[f], 0.f);
        for (int k0 = 0; k0 < 256; k0 += 32) {
            __syncthreads();
            for (int idx = tid; idx < 512; idx += 256) {
                int row = idx >> 2, k8 = (idx & 3) * 8;
                *(uint4*)(As + row * 40 + k8) =
                    *(const uint4*)&g_Wq_h[(size_t)(m0 + row) * 256 + k0 + k8];
            }
            __syncthreads();
#pragma unroll
            for (int ks = 0; ks < 32; ks += 16) {
                wmma::fragment<wmma::matrix_a, 16, 16, 16, __half, wmma::row_major> af;
                wmma::load_matrix_sync(af, As + (wid * 16) * 40 + ks, 40);
#pragma unroll
                for (int f = 0; f < 5; f++) {
                    wmma::fragment<wmma::matrix_b, 16, 16, 16, __half, wmma::col_major> bf;
                    wmma::load_matrix_sync(bf, Ks + (f * 16) * 264 + k0 + ks, 264);
                    wmma::mma_sync(acc[f], af, bf, acc[f]);
                }
            }
        }
        __syncthreads();
        float* scr = scrb + wid * 320;
#pragma unroll
        for (int f = 0; f < 5; f++) {
            wmma::store_matrix_sync(scr, acc[f], 20, wmma::mem_row_major);
            __syncwarp();
            scr_to_half(scr, g_w2 + ((size_t)bn * 512 + m0 + wid * 16) * 80 + f * 16, 80, lane);
            __syncwarp();
        }
    }
}

// ---------------- 7. attention: S = x^T W2 + b2, softmax, O = PV ----------
// grid (16 mtiles, 64 bn), 256 threads (8 warps; S/PV decode 4M x 2N).
// smem: P [64][88] h @0 (11264) | Sf [64][92] f @11264 (23552; V [80][136] reuses)
//       | staging dbuf 2 x { A[32][72] h 4608 + B[32][88] h 5632 } @34816 (20480; PV scr reuses)
#define ATT2_SMEM 55296

__global__ __launch_bounds__(256) void k_attq() {
    extern __shared__ __align__(16) char dyn[];
    __half* P  = (__half*)dyn;                      // [64][88]
    float*  Sf = (float*)(dyn + 11264);             // [64][92]
    int bn = blockIdx.y;
    int b = bn >> 4, np = bn & 15;
    int i0 = (np >> 2) * 32, j0 = (np & 3) * 32;
    int mBase = blockIdx.x * 64;
    int tid = threadIdx.x;
    int lane = tid & 31;
    int wid = tid >> 5;
    int wm = wid & 3;
    int wn = wid >> 2;
    const __half* xb = g_xh + (size_t)b * Cc * HW;
    const __half* w2 = g_w2 + (size_t)bn * 512 * 80;
    int nfr = (wn == 0) ? 3 : 2;
    int nb0 = (wn == 0) ? 0 : 48;

    // ===== phase S: S[64px][80cm] = x^T @ W2 + b2 =====
    {
        wmma::fragment<wmma::accumulator, 16, 16, 16, float> sacc[3];
        for (int f = 0; f < nfr; f++)
            wmma::load_matrix_sync(sacc[f], g_b2 + (size_t)bn * 1280 + nb0 + f * 16, 80,
                                   wmma::mem_row_major);

        auto stage = [&](int s, int k0) {
            char* base = dyn + 34816 + s * 10240;
            for (int idx = tid; idx < 576; idx += 256) {
                if (idx < 256) {
                    int ch = idx >> 3;
                    int px = (idx & 7) * 8;
                    int p = mBase + px;
                    cp16((__half*)base + ch * 72 + px,
                         xb + (size_t)(k0 + ch) * HW + (i0 + (p >> 5)) * 128 + j0 + (p & 31));
                } else {
                    int j = idx - 256;
                    int kk = j / 10;
                    int n = (j % 10) * 8;
                    cp16((__half*)(base + 4608) + kk * 88 + n,
                         w2 + (size_t)(k0 + kk) * 80 + n);
                }
            }
            cp_commit();
        };

        stage(0, 0);
        for (int it = 0; it < 16; it++) {
            if (it + 1 < 16) {
                stage((it + 1) & 1, (it + 1) * 32);
                cp_wait<1>();
            } else {
                cp_wait<0>();
            }
            __syncthreads();
            int s = it & 1;
            __half* As = (__half*)(dyn + 34816 + s * 10240);
            __half* Bs = (__half*)(dyn + 34816 + s * 10240 + 4608);
#pragma unroll
            for (int ks = 0; ks < 32; ks += 16) {
                wmma::fragment<wmma::matrix_a, 16, 16, 16, __half, wmma::col_major> af;
                wmma::load_matrix_sync(af, As + ks * 72 + wm * 16, 72);
                for (int f = 0; f < nfr; f++) {
                    wmma::fragment<wmma::matrix_b, 16, 16, 16, __half, wmma::row_major> bf;
                    wmma::load_matrix_sync(bf, Bs + ks * 88 + nb0 + f * 16, 88);
                    wmma::mma_sync(sacc[f], af, bf, sacc[f]);
                }
            }
            __syncthreads();
        }
        for (int f = 0; f < nfr; f++)
            wmma::store_matrix_sync(Sf + (wm * 16) * 92 + nb0 + f * 16, sacc[f], 92,
                                    wmma::mem_row_major);
    }
    __syncthreads();

    // ===== softmax -> P =====
    if (tid < 64) {
        const float* srow = Sf + tid * 92;
        float mx = -1e30f;
        for (int c = 0; c < 76; c++) mx = fmaxf(mx, srow[c]);
        float s = 0.f;
        float e[76];
        for (int c = 0; c < 76; c++) { e[c] = expf(srow[c] - mx); s += e[c]; }
        float inv = 1.0f / s;
        __half* prow = P + tid * 88;
        for (int c = 0; c < 76; c++) prow[c] = __float2half(e[c] * inv);
        prow[76] = __float2half(0.f);
        prow[77] = __float2half(0.f);
        prow[78] = __float2half(0.f);
        prow[79] = __float2half(0.f);
    }
    __syncthreads();

    // ===== phase PV: O = P @ V =====
    __half* Vsm = (__half*)(dyn + 11264);               // [80][136] (reuses Sf)
    float* scr2 = (float*)(dyn + 34816) + wid * 320;    // [16][20] per warp (reuses staging)
    for (int hb = 0; hb < 2; hb++) {
        for (int idx = tid; idx < 1280; idx += 256) {
            int row = idx >> 4, c8 = (idx & 15) * 8;
            uint4 z = {0, 0, 0, 0};
            uint4 val = (row < 76) ? *(const uint4*)&g_vvh[row * 256 + hb * 128 + c8] : z;
            *(uint4*)(Vsm + row * 136 + c8) = val;
        }
        __syncthreads();
        wmma::fragment<wmma::accumulator, 16, 16, 16, float> oacc[4];
#pragma unroll
        for (int j = 0; j < 4; j++) wmma::fill_fragment(oacc[j], 0.f);
#pragma unroll
        for (int kc = 0; kc < 5; kc++) {
            int ks = kc * 16;
            wmma::fragment<wmma::matrix_a, 16, 16, 16, __half, wmma::row_major> pf;
            wmma::load_matrix_sync(pf, P + (wm * 16) * 88 + ks, 88);
#pragma unroll
            for (int j = 0; j < 4; j++) {
                wmma::fragment<wmma::matrix_b, 16, 16, 16, __half, wmma::row_major> vf;
                wmma::load_matrix_sync(vf, Vsm + ks * 136 + wn * 64 + j * 16, 136);
                wmma::mma_sync(oacc[j], pf, vf, oacc[j]);
            }
        }
        __half* obase = g_oh + ((size_t)bn * 1024 + mBase + wm * 16) * 256 + hb * 128 + wn * 64;
#pragma unroll
        for (int j = 0; j < 4; j++) {
            wmma::store_matrix_sync(scr2, oacc[j], 20, wmma::mem_row_major);
            __syncwarp();
            scr_to_half(scr2, obase + j * 16, 256, lane);
            __syncwarp();
        }
        __syncthreads();
    }
}

// ---------------- 8. conv (WMMA) + BN + ReLU, patch-major A ----------------
__global__ __launch_bounds__(256, 2) void k_conv_w(const float* __restrict__ gamma,
                                                   const float* __restrict__ beta,
                                                   const float* __restrict__ mean,
                                                   const float* __restrict__ var,
                                                   float* __restrict__ y) {
    __shared__ __align__(16) union {
        struct { __half A[128][40]; __half B[32][72]; } ab;
        float C[64 * 136];
    } u;
    int nBase = blockIdx.x * 64;
    int mBase = blockIdx.y * 128;
    int tid = threadIdx.x;
    int wid = tid >> 5;
    int wm = wid & 3;
    int wn = wid >> 2;

    wmma::fragment<wmma::accumulator, 16, 16, 16, float> c[2][2];
#pragma unroll
    for (int i = 0; i < 2; i++)
#pragma unroll
        for (int j = 0; j < 2; j++) wmma::fill_fragment(c[i][j], 0.f);

    for (int k0 = 0; k0 < 256; k0 += 32) {
#pragma unroll
        for (int l = 0; l < 2; l++) {
            int idx = tid + l * 256;
            int m = idx >> 2;
            int k8 = (idx & 3) * 8;
            *(uint4*)&u.ab.A[m][k8] = *(const uint4*)&g_oh[(size_t)(mBase + m) * 256 + k0 + k8];
        }
        {
            int kk = tid >> 3;
            int n = (tid & 7) * 8;
            *(uint4*)&u.ab.B[kk][n] = *(const uint4*)&g_Wc_h[(k0 + kk) * Cc + nBase + n];
        }
        __syncthreads();
#pragma unroll
        for (int ks = 0; ks < 32; ks += 16) {
            wmma::fragment<wmma::matrix_a, 16, 16, 16, __half, wmma::row_major> af[2];
            wmma::fragment<wmma::matrix_b, 16, 16, 16, __half, wmma::row_major> bf[2];
#pragma unroll
            for (int i = 0; i < 2; i++)
                wmma::load_matrix_sync(af[i], &u.ab.A[wm * 32 + i * 16][ks], 40);
#pragma unroll
            for (int j = 0; j < 2; j++)
                wmma::load_matrix_sync(bf[j], &u.ab.B[ks][wn * 32 + j * 16], 72);
#pragma unroll
            for (int i = 0; i < 2; i++)
#pragma unroll
                for (int j = 0; j < 2; j++)
                    wmma::mma_sync(c[i][j], af[i], bf[j], c[i][j]);
        }
        __syncthreads();
    }

#pragma unroll
    for (int i = 0; i < 2; i++)
#pragma unroll
        for (int j = 0; j < 2; j++)
            wmma::store_matrix_sync(&u.C[(wn * 32 + j * 16) * 136 + wm * 32 + i * 16],
                                    c[i][j], 136, wmma::mem_col_major);
    __syncthreads();

    {
        int n = tid >> 2;
        int q4 = tid & 3;
        int ch = nBase + n;
        float iv = gamma[ch] / sqrtf(var[ch] + 1e-5f);
        float ad = beta[ch] - mean[ch] * iv;
        int bn = mBase >> 10;
        int pp0 = mBase & 1023;
        int b = bn >> 4, np = bn & 15;
        int i0 = (np >> 2) * 32, j0 = (np & 3) * 32;
        float* ybase = y + ((size_t)b * Cc + ch) * HW;
        const float* crow = &u.C[n * 136];
#pragma unroll
        for (int l = 0; l < 8; l++) {
            int m = (q4 + l * 4) * 4;
            int p = pp0 + m;
            float4 v = *(const float4*)&crow[m];
            v.x = fmaxf(v.x * iv + ad, 0.f);
            v.y = fmaxf(v.y * iv + ad, 0.f);
            v.z = fmaxf(v.z * iv + ad, 0.f);
            v.w = fmaxf(v.w * iv + ad, 0.f);
            *(float4*)&ybase[(i0 + (p >> 5)) * 128 + j0 + (p & 31)] = v;
        }
    }
}

// ---------------- launcher ----------------
extern "C" void kernel_launch(void* const* d_in, const int* in_sizes, int n_in,
                              void* d_out, int out_size) {
    const float* x   = (const float*)d_in[0];
    const float* sim = (const float*)d_in[1];
    const float* gcc = (const float*)d_in[2];
    const float* Wq  = (const float*)d_in[3];
    const float* bq  = (const float*)d_in[4];
    const float* Wk  = (const float*)d_in[5];
    const float* bk  = (const float*)d_in[6];
    const float* Wv  = (const float*)d_in[7];
    const float* bv  = (const float*)d_in[8];
    const float* Wc  = (const float*)d_in[9];
    const float* gm  = (const float*)d_in[10];
    const float* bt  = (const float*)d_in[11];
    const float* mn  = (const float*)d_in[12];
    const float* vr  = (const float*)d_in[13];
    float* y = (float*)d_out;
    float* tail = y + (size_t)Bsz * Cc * HW;

    cudaFuncSetAttribute(k_w2, cudaFuncAttributeMaxDynamicSharedMemorySize, W2_SMEM);
    cudaFuncSetAttribute(k_attq, cudaFuncAttributeMaxDynamicSharedMemorySize, ATT2_SMEM);

    k_misc<<<7244, 256>>>(x, sim, gcc, Wq, Wk, Wc, bq, Wv, bv, tail);
    k_local_w<<<dim3(4, 64), 320>>>();
    k_kproj_w<<<dim3(2, 64), 320>>>(bk);
    k_w2<<<64, 256, W2_SMEM>>>(bq);
    k_attq<<<dim3(16, 64), 256, ATT2_SMEM>>>();
    k_conv_w<<<dim3(8, 512), 256>>>(gm, bt, mn, vr, y);
}

// round 14
// speedup vs baseline: 1.0775x; 1.0775x over previous
#include <cuda_runtime.h>
#include <cuda_fp16.h>
#include <mma.h>
#include <math.h>

using namespace nvcuda;

#define Bsz 4
#define Cc 512
#define MID 256
#define CMn 76
#define Hh 128
#define Ww 128
#define HW 16384
#define Pp 1024
#define Np 16

// ---------------- static scratch ----------------
__device__ float  g_pool[Bsz * CMn * Np];
__device__ __half g_smxh[(size_t)64 * 80 * 1024];       // softmax(sim), padded 80 rows
__device__ __half g_localh[(size_t)64 * 80 * 512];      // local (conf folded), padded
__device__ __half g_kkh[(size_t)64 * 76 * 256];         // k proj (half)
__device__ __half g_vvh[76 * 256];                      // v proj (half)
__device__ __half g_oh[(size_t)64 * 1024 * 256];        // attn out HALF, patch-major
__device__ __half g_xh[(size_t)Bsz * Cc * HW];          // x as half
__device__ __half g_Wq_h[Cc * MID];
__device__ __half g_Wk_h[Cc * MID];
__device__ __half g_Wc_h[MID * Cc];
__device__ float  g_qbias[16 * MID];
__device__ __half g_w2[(size_t)64 * 512 * 80];          // W2 = Wq @ K^T per bn [ch][cm]
__device__ float  g_b2[64 * 16 * 80];                   // b2 = bq @ K^T, replicated 16 rows

// ---------------- cp.async helpers ----------------
__device__ __forceinline__ void cp16(void* dst, const void* src) {
    unsigned d = (unsigned)__cvta_generic_to_shared(dst);
    asm volatile("cp.async.ca.shared.global [%0], [%1], 16;\n" :: "r"(d), "l"(src));
}
__device__ __forceinline__ void cp_commit() { asm volatile("cp.async.commit_group;\n"); }
template <int N>
__device__ __forceinline__ void cp_wait() { asm volatile("cp.async.wait_group %0;\n" :: "n"(N)); }

// convert a 16x16 fp32 warp scratch tile (ld=20) to half and write out (ldg mult of 8).
__device__ __forceinline__ void scr_to_half(const float* scr, __half* gdst, int ldg, int lane) {
    int rr = lane >> 1, c8 = (lane & 1) * 8;
    const float* s = scr + rr * 20 + c8;
    __half2 h0 = __floats2half2_rn(s[0], s[1]);
    __half2 h1 = __floats2half2_rn(s[2], s[3]);
    __half2 h2 = __floats2half2_rn(s[4], s[5]);
    __half2 h3 = __floats2half2_rn(s[6], s[7]);
    uint4 o;
    o.x = *(unsigned*)&h0; o.y = *(unsigned*)&h1;
    o.z = *(unsigned*)&h2; o.w = *(unsigned*)&h3;
    *(uint4*)(gdst + (size_t)rr * ldg + c8) = o;
}

// ---------------- 0. merged misc: setup + x->half + pool/softmax + v -------
__global__ void k_misc(const float* __restrict__ x, const float* __restrict__ sim,
                       const float* __restrict__ gcc,
                       const float* __restrict__ Wq, const float* __restrict__ Wk,
                       const float* __restrict__ Wc, const float* __restrict__ bq,
                       const float* __restrict__ Wv, const float* __restrict__ bv,
                       float* __restrict__ out_tail) {
    __shared__ float red[256];
    __shared__ float sg[512];
    int blk = blockIdx.x;
    int t = threadIdx.x;

    if (blk < 256) {
        int g = blk * 256 + t;
        int stride = 256 * 256;
        for (int i = g; i < Cc * MID; i += stride) {
            g_Wq_h[i] = __float2half(Wq[i]);
            g_Wk_h[i] = __float2half(Wk[i]);
            g_Wc_h[i] = __float2half(Wc[i]);
        }
        for (int i = g; i < 16 * MID; i += stride) g_qbias[i] = bq[i & (MID - 1)];
        for (int i = g; i < 64 * 4 * 1024; i += stride) {
            int bn = i >> 12, rem = i & 4095;
            g_smxh[((size_t)bn * 80 + 76) * 1024 + rem] = __float2half(0.f);
        }
        for (int i = g; i < 64 * 4 * 512; i += stride) {
            int bn = i >> 11, rem = i & 2047;
            g_localh[((size_t)bn * 80 + 76) * 512 + rem] = __float2half(0.f);
        }
    } else if (blk < 2304) {
        size_t n8 = (size_t)Bsz * Cc * HW / 8;
        size_t g = (size_t)(blk - 256) * 256 + t;
        size_t stride = (size_t)2048 * 256;
        for (; g < n8; g += stride) {
            const float4* s = (const float4*)x + g * 2;
            float4 a = s[0], b = s[1];
            __half2 h0 = __floats2half2_rn(a.x, a.y);
            __half2 h1 = __floats2half2_rn(a.z, a.w);
            __half2 h2 = __floats2half2_rn(b.x, b.y);
            __half2 h3 = __floats2half2_rn(b.z, b.w);
            uint4 o;
            o.x = *(unsigned*)&h0; o.y = *(unsigned*)&h1;
            o.z = *(unsigned*)&h2; o.w = *(unsigned*)&h3;
            ((uint4*)g_xh)[g] = o;
        }
    } else if (blk < 7168) {
        int id = blk - 2304;
        int cm = id % CMn;
        int bn = id / CMn;
        int n = bn & 15, b = bn >> 4;
        int i0 = (n >> 2) * 32, j0 = (n & 3) * 32;
        const float* base = sim + ((size_t)b * CMn + cm) * HW;
        float v[4];
        float mx = -1e30f, sraw = 0.f;
#pragma unroll
        for (int it = 0; it < 4; it++) {
            int p = t + it * 256;
            int pi = p >> 5, pj = p & 31;
            v[it] = base[(i0 + pi) * Ww + j0 + pj];
            mx = fmaxf(mx, v[it]);
            sraw += v[it];
        }
        red[t] = sraw; __syncthreads();
        for (int o = 128; o > 0; o >>= 1) {
            if (t < o) red[t] += red[t + o];
            __syncthreads();
        }
        if (t == 0) {
            float m = red[0] * (1.0f / 1024.0f);
            int pid = (b * CMn + cm) * 16 + n;
            g_pool[pid] = m;
            out_tail[pid] = m;
        }
        __syncthreads();
        red[t] = mx; __syncthreads();
        for (int o = 128; o > 0; o >>= 1) {
            if (t < o) red[t] = fmaxf(red[t], red[t + o]);
            __syncthreads();
        }
        float gmx = red[0]; __syncthreads();
        float s = 0.f;
#pragma unroll
        for (int it = 0; it < 4; it++) { v[it] = expf(v[it] - gmx); s += v[it]; }
        red[t] = s; __syncthreads();
        for (int o = 128; o > 0; o >>= 1) {
            if (t < o) red[t] += red[t + o];
            __syncthreads();
        }
        float inv = 1.0f / red[0];
        __half* dst = g_smxh + ((size_t)bn * 80 + cm) * Pp;
#pragma unroll
        for (int it = 0; it < 4; it++) { int p = t + it * 256; dst[p] = __float2half(v[it] * inv); }
    } else {
        int c = blk - 7168;
        for (int k = t; k < 512; k += 256) sg[k] = gcc[c * 512 + k];
        __syncthreads();
        float acc = 0.f;
        for (int k = 0; k < 512; k++) acc += sg[k] * Wv[k * MID + t];
        g_vvh[c * MID + t] = __float2half(acc + bv[t]);
    }
}

// ---------------- 3. local = smx^T @ xs * conf  (WMMA, cp.async x2) --------
__device__ __forceinline__ void local_stage(int tid, __half* Adst, __half* Bdst,
                                            const __half* Asrc, const __half* Bsrc,
                                            int it, int nBase, int baseoff) {
    for (int idx = tid; idx < 832; idx += 320) {
        if (idx < 320) {
            int row = idx >> 2, col = (idx & 3) * 8;
            cp16(Adst + row * 40 + col, Asrc + (size_t)row * 1024 + it * 32 + col);
        } else {
            int j = idx - 320;
            int row = j >> 2, col = (j & 3) * 8;
            cp16(Bdst + row * 40 + col,
                 Bsrc + (size_t)(nBase + row) * HW + baseoff + it * Ww + col);
        }
    }
    cp_commit();
}

__global__ __launch_bounds__(320, 2) void k_local_w() {
    __shared__ __align__(16) union {
        struct { __half A[2][80][40]; __half B[2][128][40]; } s;
        float C[80 * 136];
    } u;
    int bn = blockIdx.y;
    int b = bn >> 4, np = bn & 15;
    int i0 = (np >> 2) * 32, j0 = (np & 3) * 32;
    int baseoff = i0 * Ww + j0;
    int nBase = blockIdx.x * 128;
    const __half* Asrc = g_smxh + (size_t)bn * 80 * 1024;
    const __half* Bsrc = g_xh + (size_t)b * Cc * HW;
    int tid = threadIdx.x;
    int wid = tid >> 5;
    int wm = wid % 5, wn = wid / 5;

    wmma::fragment<wmma::accumulator, 16, 16, 16, float> c[4];
#pragma unroll
    for (int j = 0; j < 4; j++) wmma::fill_fragment(c[j], 0.f);

    local_stage(tid, &u.s.A[0][0][0], &u.s.B[0][0][0], Asrc, Bsrc, 0, nBase, baseoff);
    for (int it = 0; it < 32; it++) {
        if (it + 1 < 32) {
            int s2 = (it + 1) & 1;
            local_stage(tid, &u.s.A[s2][0][0], &u.s.B[s2][0][0], Asrc, Bsrc, it + 1, nBase, baseoff);
            cp_wait<1>();
        } else {
            cp_wait<0>();
        }
        __syncthreads();
        int s = it & 1;
#pragma unroll
        for (int ks = 0; ks < 32; ks += 16) {
            wmma::fragment<wmma::matrix_a, 16, 16, 16, __half, wmma::row_major> af;
            wmma::load_matrix_sync(af, &u.s.A[s][wm * 16][ks], 40);
#pragma unroll
            for (int j = 0; j < 4; j++) {
                wmma::fragment<wmma::matrix_b, 16, 16, 16, __half, wmma::col_major> bf;
                wmma::load_matrix_sync(bf, &u.s.B[s][wn * 64 + j * 16][ks], 40);
                wmma::mma_sync(c[j], af, bf, c[j]);
            }
        }
        __syncthreads();
    }
#pragma unroll
    for (int j = 0; j < 4; j++)
        wmma::store_matrix_sync(&u.C[(wm * 16) * 136 + wn * 64 + j * 16], c[j], 136,
                                wmma::mem_row_major);
    __syncthreads();
    for (int idx = tid; idx < 76 * 128; idx += 320) {
        int cc = idx >> 7, nn = idx & 127;
        float conf = g_pool[(b * CMn + cc) * 16 + np];
        g_localh[((size_t)bn * 80 + cc) * 512 + nBase + nn] =
            __float2half(u.C[cc * 136 + nn] * conf);
    }
}

// ---------------- 4. k = local @ Wk + bk (WMMA, half out) ----------------
__global__ __launch_bounds__(320, 2) void k_kproj_w(const float* __restrict__ bk) {
    __shared__ __align__(16) union {
        struct { __half A[80][40]; __half B[32][136]; } ab;
        float C[80 * 136];
    } u;
    int bn = blockIdx.y;
    int nBase = blockIdx.x * 128;
    const __half* Ap = g_localh + (size_t)bn * 80 * 512;
    int tid = threadIdx.x;
    int wid = tid >> 5;
    int wm = wid % 5, wn = wid / 5;

    wmma::fragment<wmma::accumulator, 16, 16, 16, float> c[4];
#pragma unroll
    for (int j = 0; j < 4; j++) wmma::fill_fragment(c[j], 0.f);

    for (int k0 = 0; k0 < 512; k0 += 32) {
        {
            int cc = tid >> 2;
            int h8 = (tid & 3) * 8;
            *(uint4*)&u.ab.A[cc][h8] = *(const uint4*)&Ap[(size_t)cc * 512 + k0 + h8];
        }
        for (int idx = tid; idx < 512; idx += 320) {
            int kk = idx >> 4;
            int nn = (idx & 15) * 8;
            *(uint4*)&u.ab.B[kk][nn] = *(const uint4*)&g_Wk_h[(k0 + kk) * MID + nBase + nn];
        }
        __syncthreads();
#pragma unroll
        for (int ks = 0; ks < 32; ks += 16) {
            wmma::fragment<wmma::matrix_a, 16, 16, 16, __half, wmma::row_major> af;
            wmma::load_matrix_sync(af, &u.ab.A[wm * 16][ks], 40);
#pragma unroll
            for (int j = 0; j < 4; j++) {
                wmma::fragment<wmma::matrix_b, 16, 16, 16, __half, wmma::row_major> bf;
                wmma::load_matrix_sync(bf, &u.ab.B[ks][wn * 64 + j * 16], 136);
                wmma::mma_sync(c[j], af, bf, c[j]);
            }
        }
        __syncthreads();
    }
#pragma unroll
    for (int j = 0; j < 4; j++)
        wmma::store_matrix_sync(&u.C[(wm * 16) * 136 + wn * 64 + j * 16], c[j], 136,
                                wmma::mem_row_major);
    __syncthreads();
    for (int idx = tid; idx < 76 * 128; idx += 320) {
        int cc = idx >> 7, nn = idx & 127;
        g_kkh[((size_t)bn * 76 + cc) * 256 + nBase + nn] =
            __float2half(u.C[cc * 136 + nn] + bk[nBase + nn]);
    }
}

// ---------------- 5. W2 = Wq @ K^T per bn, plus b2 = bq @ K^T --------------
// grid (4 mchunks, 64 bn), block 256 (8 warps). Each block: 128 rows of W2.
// smem: Ks [80][264] (42240) + union{As[128][40], scr} (10240)
#define W2_SMEM 52480

__global__ __launch_bounds__(256, 2) void k_w2(const float* __restrict__ bq) {
    extern __shared__ __align__(16) char dynw[];
    __half* Ks = (__half*)dynw;                 // [80][264]
    __half* As = (__half*)(dynw + 42240);       // [128][40]
    float* scrb = (float*)(dynw + 42240);       // 8 x [16][20]
    int m0 = blockIdx.x * 128;
    int bn = blockIdx.y;
    int tid = threadIdx.x;
    int lane = tid & 31;
    int wid = tid >> 5;
    const __half* ksrc = g_kkh + (size_t)bn * 76 * 256;

    // load K (80 rows, zero-padded)
    for (int idx = tid; idx < 2560; idx += 256) {
        int row = idx >> 5, c8 = (idx & 31) * 8;
        uint4 z = {0, 0, 0, 0};
        uint4 val = (row < 76) ? *(const uint4*)&ksrc[(size_t)row * 256 + c8] : z;
        *(uint4*)(Ks + row * 264 + c8) = val;
    }
    __syncthreads();

    // b2 only from the m0==0 block
    if (blockIdx.x == 0 && tid < 80) {
        float s = 0.f;
        for (int mid = 0; mid < 256; mid++) s += bq[mid] * __half2float(Ks[tid * 264 + mid]);
        for (int r = 0; r < 16; r++) g_b2[(size_t)bn * 1280 + r * 80 + tid] = s;
    }

    // W2[m0+row][c] = sum_mid Wq[m0+row][mid] * K[c][mid]
    wmma::fragment<wmma::accumulator, 16, 16, 16, float> acc[5];
#pragma unroll
    for (int f = 0; f < 5; f++) wmma::fill_fragment(acc[f], 0.f);
    for (int k0 = 0; k0 < 256; k0 += 32) {
        __syncthreads();
        for (int idx = tid; idx < 512; idx += 256) {
            int row = idx >> 2, k8 = (idx & 3) * 8;
            *(uint4*)(As + row * 40 + k8) =
                *(const uint4*)&g_Wq_h[(size_t)(m0 + row) * 256 + k0 + k8];
        }
        __syncthreads();
#pragma unroll
        for (int ks = 0; ks < 32; ks += 16) {
            wmma::fragment<wmma::matrix_a, 16, 16, 16, __half, wmma::row_major> af;
            wmma::load_matrix_sync(af, As + (wid * 16) * 40 + ks, 40);
#pragma unroll
            for (int f = 0; f < 5; f++) {
                wmma::fragment<wmma::matrix_b, 16, 16, 16, __half, wmma::col_major> bf;
                wmma::load_matrix_sync(bf, Ks + (f * 16) * 264 + k0 + ks, 264);
                wmma::mma_sync(acc[f], af, bf, acc[f]);
            }
        }
    }
    __syncthreads();
    float* scr = scrb + wid * 320;
#pragma unroll
    for (int f = 0; f < 5; f++) {
        wmma::store_matrix_sync(scr, acc[f], 20, wmma::mem_row_major);
        __syncwarp();
        scr_to_half(scr, g_w2 + ((size_t)bn * 512 + m0 + wid * 16) * 80 + f * 16, 80, lane);
        __syncwarp();
    }
}

// ---------------- 7. attention: S = x^T W2 + b2, softmax, O = PV ----------
// grid (16 mtiles, 64 bn), 256 threads (8 warps; S/PV decode 4M x 2N).
#define ATT2_SMEM 55296

__global__ __launch_bounds__(256) void k_attq() {
    extern __shared__ __align__(16) char dyn[];
    __half* P  = (__half*)dyn;                      // [64][88]
    float*  Sf = (float*)(dyn + 11264);             // [64][92]
    int bn = blockIdx.y;
    int b = bn >> 4, np = bn & 15;
    int i0 = (np >> 2) * 32, j0 = (np & 3) * 32;
    int mBase = blockIdx.x * 64;
    int tid = threadIdx.x;
    int lane = tid & 31;
    int wid = tid >> 5;
    int wm = wid & 3;
    int wn = wid >> 2;
    const __half* xb = g_xh + (size_t)b * Cc * HW;
    const __half* w2 = g_w2 + (size_t)bn * 512 * 80;
    int nfr = (wn == 0) ? 3 : 2;
    int nb0 = (wn == 0) ? 0 : 48;

    // ===== phase S: S[64px][80cm] = x^T @ W2 + b2 =====
    {
        wmma::fragment<wmma::accumulator, 16, 16, 16, float> sacc[3];
        for (int f = 0; f < nfr; f++)
            wmma::load_matrix_sync(sacc[f], g_b2 + (size_t)bn * 1280 + nb0 + f * 16, 80,
                                   wmma::mem_row_major);

        auto stage = [&](int s, int k0) {
            char* base = dyn + 34816 + s * 10240;
            for (int idx = tid; idx < 576; idx += 256) {
                if (idx < 256) {
                    int ch = idx >> 3;
                    int px = (idx & 7) * 8;
                    int p = mBase + px;
                    cp16((__half*)base + ch * 72 + px,
                         xb + (size_t)(k0 + ch) * HW + (i0 + (p >> 5)) * 128 + j0 + (p & 31));
                } else {
                    int j = idx - 256;
                    int kk = j / 10;
                    int n = (j % 10) * 8;
                    cp16((__half*)(base + 4608) + kk * 88 + n,
                         w2 + (size_t)(k0 + kk) * 80 + n);
                }
            }
            cp_commit();
        };

        stage(0, 0);
        for (int it = 0; it < 16; it++) {
            if (it + 1 < 16) {
                stage((it + 1) & 1, (it + 1) * 32);
                cp_wait<1>();
            } else {
                cp_wait<0>();
            }
            __syncthreads();
            int s = it & 1;
            __half* As = (__half*)(dyn + 34816 + s * 10240);
            __half* Bs = (__half*)(dyn + 34816 + s * 10240 + 4608);
#pragma unroll
            for (int ks = 0; ks < 32; ks += 16) {
                wmma::fragment<wmma::matrix_a, 16, 16, 16, __half, wmma::col_major> af;
                wmma::load_matrix_sync(af, As + ks * 72 + wm * 16, 72);
                for (int f = 0; f < nfr; f++) {
                    wmma::fragment<wmma::matrix_b, 16, 16, 16, __half, wmma::row_major> bf;
                    wmma::load_matrix_sync(bf, Bs + ks * 88 + nb0 + f * 16, 88);
                    wmma::mma_sync(sacc[f], af, bf, sacc[f]);
                }
            }
            __syncthreads();
        }
        for (int f = 0; f < nfr; f++)
            wmma::store_matrix_sync(Sf + (wm * 16) * 92 + nb0 + f * 16, sacc[f], 92,
                                    wmma::mem_row_major);
    }
    __syncthreads();

    // ===== softmax -> P =====
    if (tid < 64) {
        const float* srow = Sf + tid * 92;
        float mx = -1e30f;
        for (int c = 0; c < 76; c++) mx = fmaxf(mx, srow[c]);
        float s = 0.f;
        float e[76];
        for (int c = 0; c < 76; c++) { e[c] = expf(srow[c] - mx); s += e[c]; }
        float inv = 1.0f / s;
        __half* prow = P + tid * 88;
        for (int c = 0; c < 76; c++) prow[c] = __float2half(e[c] * inv);
        prow[76] = __float2half(0.f);
        prow[77] = __float2half(0.f);
        prow[78] = __float2half(0.f);
        prow[79] = __float2half(0.f);
    }
    __syncthreads();

    // ===== phase PV: O = P @ V =====
    __half* Vsm = (__half*)(dyn + 11264);               // [80][136] (reuses Sf)
    float* scr2 = (float*)(dyn + 34816) + wid * 320;    // [16][20] per warp (reuses staging)
    for (int hb = 0; hb < 2; hb++) {
        for (int idx = tid; idx < 1280; idx += 256) {
            int row = idx >> 4, c8 = (idx & 15) * 8;
            uint4 z = {0, 0, 0, 0};
            uint4 val = (row < 76) ? *(const uint4*)&g_vvh[row * 256 + hb * 128 + c8] : z;
            *(uint4*)(Vsm + row * 136 + c8) = val;
        }
        __syncthreads();
        wmma::fragment<wmma::accumulator, 16, 16, 16, float> oacc[4];
#pragma unroll
        for (int j = 0; j < 4; j++) wmma::fill_fragment(oacc[j], 0.f);
#pragma unroll
        for (int kc = 0; kc < 5; kc++) {
            int ks = kc * 16;
            wmma::fragment<wmma::matrix_a, 16, 16, 16, __half, wmma::row_major> pf;
            wmma::load_matrix_sync(pf, P + (wm * 16) * 88 + ks, 88);
#pragma unroll
            for (int j = 0; j < 4; j++) {
                wmma::fragment<wmma::matrix_b, 16, 16, 16, __half, wmma::row_major> vf;
                wmma::load_matrix_sync(vf, Vsm + ks * 136 + wn * 64 + j * 16, 136);
                wmma::mma_sync(oacc[j], pf, vf, oacc[j]);
            }
        }
        __half* obase = g_oh + ((size_t)bn * 1024 + mBase + wm * 16) * 256 + hb * 128 + wn * 64;
#pragma unroll
        for (int j = 0; j < 4; j++) {
            wmma::store_matrix_sync(scr2, oacc[j], 20, wmma::mem_row_major);
            __syncwarp();
            scr_to_half(scr2, obase + j * 16, 256, lane);
            __syncwarp();
        }
        __syncthreads();
    }
}

// ---------------- 8. conv (WMMA) + BN + ReLU, patch-major A ----------------
__global__ __launch_bounds__(256, 2) void k_conv_w(const float* __restrict__ gamma,
                                                   const float* __restrict__ beta,
                                                   const float* __restrict__ mean,
                                                   const float* __restrict__ var,
                                                   float* __restrict__ y) {
    __shared__ __align__(16) union {
        struct { __half A[128][40]; __half B[32][72]; } ab;
        float C[64 * 136];
    } u;
    int nBase = blockIdx.x * 64;
    int mBase = blockIdx.y * 128;
    int tid = threadIdx.x;
    int wid = tid >> 5;
    int wm = wid & 3;
    int wn = wid >> 2;

    wmma::fragment<wmma::accumulator, 16, 16, 16, float> c[2][2];
#pragma unroll
    for (int i = 0; i < 2; i++)
#pragma unroll
        for (int j = 0; j < 2; j++) wmma::fill_fragment(c[i][j], 0.f);

    for (int k0 = 0; k0 < 256; k0 += 32) {
#pragma unroll
        for (int l = 0; l < 2; l++) {
            int idx = tid + l * 256;
            int m = idx >> 2;
            int k8 = (idx & 3) * 8;
            *(uint4*)&u.ab.A[m][k8] = *(const uint4*)&g_oh[(size_t)(mBase + m) * 256 + k0 + k8];
        }
        {
            int kk = tid >> 3;
            int n = (tid & 7) * 8;
            *(uint4*)&u.ab.B[kk][n] = *(const uint4*)&g_Wc_h[(k0 + kk) * Cc + nBase + n];
        }
        __syncthreads();
#pragma unroll
        for (int ks = 0; ks < 32; ks += 16) {
            wmma::fragment<wmma::matrix_a, 16, 16, 16, __half, wmma::row_major> af[2];
            wmma::fragment<wmma::matrix_b, 16, 16, 16, __half, wmma::row_major> bf[2];
#pragma unroll
            for (int i = 0; i < 2; i++)
                wmma::load_matrix_sync(af[i], &u.ab.A[wm * 32 + i * 16][ks], 40);
#pragma unroll
            for (int j = 0; j < 2; j++)
                wmma::load_matrix_sync(bf[j], &u.ab.B[ks][wn * 32 + j * 16], 72);
#pragma unroll
            for (int i = 0; i < 2; i++)
#pragma unroll
                for (int j = 0; j < 2; j++)
                    wmma::mma_sync(c[i][j], af[i], bf[j], c[i][j]);
        }
        __syncthreads();
    }

#pragma unroll
    for (int i = 0; i < 2; i++)
#pragma unroll
        for (int j = 0; j < 2; j++)
            wmma::store_matrix_sync(&u.C[(wn * 32 + j * 16) * 136 + wm * 32 + i * 16],
                                    c[i][j], 136, wmma::mem_col_major);
    __syncthreads();

    {
        int n = tid >> 2;
        int q4 = tid & 3;
        int ch = nBase + n;
        float iv = gamma[ch] / sqrtf(var[ch] + 1e-5f);
        float ad = beta[ch] - mean[ch] * iv;
        int bn = mBase >> 10;
        int pp0 = mBase & 1023;
        int b = bn >> 4, np = bn & 15;
        int i0 = (np >> 2) * 32, j0 = (np & 3) * 32;
        float* ybase = y + ((size_t)b * Cc + ch) * HW;
        const float* crow = &u.C[n * 136];
#pragma unroll
        for (int l = 0; l < 8; l++) {
            int m = (q4 + l * 4) * 4;
            int p = pp0 + m;
            float4 v = *(const float4*)&crow[m];
            v.x = fmaxf(v.x * iv + ad, 0.f);
            v.y = fmaxf(v.y * iv + ad, 0.f);
            v.z = fmaxf(v.z * iv + ad, 0.f);
            v.w = fmaxf(v.w * iv + ad, 0.f);
            *(float4*)&ybase[(i0 + (p >> 5)) * 128 + j0 + (p & 31)] = v;
        }
    }
}

// ---------------- launcher ----------------
extern "C" void kernel_launch(void* const* d_in, const int* in_sizes, int n_in,
                              void* d_out, int out_size) {
    const float* x   = (const float*)d_in[0];
    const float* sim = (const float*)d_in[1];
    const float* gcc = (const float*)d_in[2];
    const float* Wq  = (const float*)d_in[3];
    const float* bq  = (const float*)d_in[4];
    const float* Wk  = (const float*)d_in[5];
    const float* bk  = (const float*)d_in[6];
    const float* Wv  = (const float*)d_in[7];
    const float* bv  = (const float*)d_in[8];
    const float* Wc  = (const float*)d_in[9];
    const float* gm  = (const float*)d_in[10];
    const float* bt  = (const float*)d_in[11];
    const float* mn  = (const float*)d_in[12];
    const float* vr  = (const float*)d_in[13];
    float* y = (float*)d_out;
    float* tail = y + (size_t)Bsz * Cc * HW;

    cudaFuncSetAttribute(k_w2, cudaFuncAttributeMaxDynamicSharedMemorySize, W2_SMEM);
    cudaFuncSetAttribute(k_attq, cudaFuncAttributeMaxDynamicSharedMemorySize, ATT2_SMEM);

    k_misc<<<7244, 256>>>(x, sim, gcc, Wq, Wk, Wc, bq, Wv, bv, tail);
    k_local_w<<<dim3(4, 64), 320>>>();
    k_kproj_w<<<dim3(2, 64), 320>>>(bk);
    k_w2<<<dim3(4, 64), 256, W2_SMEM>>>(bq);
    k_attq<<<dim3(16, 64), 256, ATT2_SMEM>>>();
    k_conv_w<<<dim3(8, 512), 256>>>(gm, bt, mn, vr, y);
}

// round 15
// speedup vs baseline: 1.0994x; 1.0203x over previous
#include <cuda_runtime.h>
#include <cuda_fp16.h>
#include <mma.h>
#include <math.h>

using namespace nvcuda;

#define Bsz 4
#define Cc 512
#define MID 256
#define CMn 76
#define Hh 128
#define Ww 128
#define HW 16384
#define Pp 1024
#define Np 16

// ---------------- static scratch ----------------
__device__ float  g_pool[Bsz * CMn * Np];
__device__ __half g_smxh[(size_t)64 * 80 * 1024];       // softmax(sim), padded 80 rows
__device__ __half g_localh[(size_t)64 * 80 * 512];      // local (conf folded), padded
__device__ __half g_kkh[(size_t)64 * 76 * 256];         // k proj (half)
__device__ __half g_vvh[76 * 256];                      // v proj (half)
__device__ __half g_xh[(size_t)Bsz * Cc * HW];          // x as half
__device__ __half g_Wq_h[Cc * MID];
__device__ __half g_Wk_h[Cc * MID];
__device__ __half g_Wc_h[MID * Cc];
__device__ __half g_w2[(size_t)64 * 512 * 80];          // W2 = Wq @ K^T per bn [ch][cm]
__device__ float  g_b2[64 * 16 * 80];                   // b2 = bq @ K^T, replicated 16 rows

// ---------------- cp.async helpers ----------------
__device__ __forceinline__ void cp16(void* dst, const void* src) {
    unsigned d = (unsigned)__cvta_generic_to_shared(dst);
    asm volatile("cp.async.ca.shared.global [%0], [%1], 16;\n" :: "r"(d), "l"(src));
}
__device__ __forceinline__ void cp_commit() { asm volatile("cp.async.commit_group;\n"); }
template <int N>
__device__ __forceinline__ void cp_wait() { asm volatile("cp.async.wait_group %0;\n" :: "n"(N)); }

// convert a 16x16 fp32 warp scratch tile (ld=20) to half and write out (ldg mult of 8).
__device__ __forceinline__ void scr_to_half(const float* scr, __half* gdst, int ldg, int lane) {
    int rr = lane >> 1, c8 = (lane & 1) * 8;
    const float* s = scr + rr * 20 + c8;
    __half2 h0 = __floats2half2_rn(s[0], s[1]);
    __half2 h1 = __floats2half2_rn(s[2], s[3]);
    __half2 h2 = __floats2half2_rn(s[4], s[5]);
    __half2 h3 = __floats2half2_rn(s[6], s[7]);
    uint4 o;
    o.x = *(unsigned*)&h0; o.y = *(unsigned*)&h1;
    o.z = *(unsigned*)&h2; o.w = *(unsigned*)&h3;
    *(uint4*)(gdst + (size_t)rr * ldg + c8) = o;
}

// ---------------- 0. merged misc: setup + x->half + pool/softmax + v -------
__global__ void k_misc(const float* __restrict__ x, const float* __restrict__ sim,
                       const float* __restrict__ gcc,
                       const float* __restrict__ Wq, const float* __restrict__ Wk,
                       const float* __restrict__ Wc,
                       const float* __restrict__ Wv, const float* __restrict__ bv,
                       float* __restrict__ out_tail) {
    __shared__ float red[256];
    __shared__ float sg[512];
    int blk = blockIdx.x;
    int t = threadIdx.x;

    if (blk < 256) {
        int g = blk * 256 + t;
        int stride = 256 * 256;
        for (int i = g; i < Cc * MID; i += stride) {
            g_Wq_h[i] = __float2half(Wq[i]);
            g_Wk_h[i] = __float2half(Wk[i]);
            g_Wc_h[i] = __float2half(Wc[i]);
        }
        for (int i = g; i < 64 * 4 * 1024; i += stride) {
            int bn = i >> 12, rem = i & 4095;
            g_smxh[((size_t)bn * 80 + 76) * 1024 + rem] = __float2half(0.f);
        }
        for (int i = g; i < 64 * 4 * 512; i += stride) {
            int bn = i >> 11, rem = i & 2047;
            g_localh[((size_t)bn * 80 + 76) * 512 + rem] = __float2half(0.f);
        }
    } else if (blk < 2304) {
        size_t n8 = (size_t)Bsz * Cc * HW / 8;
        size_t g = (size_t)(blk - 256) * 256 + t;
        size_t stride = (size_t)2048 * 256;
        for (; g < n8; g += stride) {
            const float4* s = (const float4*)x + g * 2;
            float4 a = s[0], b = s[1];
            __half2 h0 = __floats2half2_rn(a.x, a.y);
            __half2 h1 = __floats2half2_rn(a.z, a.w);
            __half2 h2 = __floats2half2_rn(b.x, b.y);
            __half2 h3 = __floats2half2_rn(b.z, b.w);
            uint4 o;
            o.x = *(unsigned*)&h0; o.y = *(unsigned*)&h1;
            o.z = *(unsigned*)&h2; o.w = *(unsigned*)&h3;
            ((uint4*)g_xh)[g] = o;
        }
    } else if (blk < 7168) {
        int id = blk - 2304;
        int cm = id % CMn;
        int bn = id / CMn;
        int n = bn & 15, b = bn >> 4;
        int i0 = (n >> 2) * 32, j0 = (n & 3) * 32;
        const float* base = sim + ((size_t)b * CMn + cm) * HW;
        float v[4];
        float mx = -1e30f, sraw = 0.f;
#pragma unroll
        for (int it = 0; it < 4; it++) {
            int p = t + it * 256;
            int pi = p >> 5, pj = p & 31;
            v[it] = base[(i0 + pi) * Ww + j0 + pj];
            mx = fmaxf(mx, v[it]);
            sraw += v[it];
        }
        red[t] = sraw; __syncthreads();
        for (int o = 128; o > 0; o >>= 1) {
            if (t < o) red[t] += red[t + o];
            __syncthreads();
        }
        if (t == 0) {
            float m = red[0] * (1.0f / 1024.0f);
            int pid = (b * CMn + cm) * 16 + n;
            g_pool[pid] = m;
            out_tail[pid] = m;
        }
        __syncthreads();
        red[t] = mx; __syncthreads();
        for (int o = 128; o > 0; o >>= 1) {
            if (t < o) red[t] = fmaxf(red[t], red[t + o]);
            __syncthreads();
        }
        float gmx = red[0]; __syncthreads();
        float s = 0.f;
#pragma unroll
        for (int it = 0; it < 4; it++) { v[it] = expf(v[it] - gmx); s += v[it]; }
        red[t] = s; __syncthreads();
        for (int o = 128; o > 0; o >>= 1) {
            if (t < o) red[t] += red[t + o];
            __syncthreads();
        }
        float inv = 1.0f / red[0];
        __half* dst = g_smxh + ((size_t)bn * 80 + cm) * Pp;
#pragma unroll
        for (int it = 0; it < 4; it++) { int p = t + it * 256; dst[p] = __float2half(v[it] * inv); }
    } else {
        int c = blk - 7168;
        for (int k = t; k < 512; k += 256) sg[k] = gcc[c * 512 + k];
        __syncthreads();
        float acc = 0.f;
        for (int k = 0; k < 512; k++) acc += sg[k] * Wv[k * MID + t];
        g_vvh[c * MID + t] = __float2half(acc + bv[t]);
    }
}

// ---------------- 3. local = smx^T @ xs * conf  (WMMA, cp.async x2) --------
__device__ __forceinline__ void local_stage(int tid, __half* Adst, __half* Bdst,
                                            const __half* Asrc, const __half* Bsrc,
                                            int it, int nBase, int baseoff) {
    for (int idx = tid; idx < 832; idx += 320) {
        if (idx < 320) {
            int row = idx >> 2, col = (idx & 3) * 8;
            cp16(Adst + row * 40 + col, Asrc + (size_t)row * 1024 + it * 32 + col);
        } else {
            int j = idx - 320;
            int row = j >> 2, col = (j & 3) * 8;
            cp16(Bdst + row * 40 + col,
                 Bsrc + (size_t)(nBase + row) * HW + baseoff + it * Ww + col);
        }
    }
    cp_commit();
}

__global__ __launch_bounds__(320, 2) void k_local_w() {
    __shared__ __align__(16) union {
        struct { __half A[2][80][40]; __half B[2][128][40]; } s;
        float C[80 * 136];
    } u;
    int bn = blockIdx.y;
    int b = bn >> 4, np = bn & 15;
    int i0 = (np >> 2) * 32, j0 = (np & 3) * 32;
    int baseoff = i0 * Ww + j0;
    int nBase = blockIdx.x * 128;
    const __half* Asrc = g_smxh + (size_t)bn * 80 * 1024;
    const __half* Bsrc = g_xh + (size_t)b * Cc * HW;
    int tid = threadIdx.x;
    int wid = tid >> 5;
    int wm = wid % 5, wn = wid / 5;

    wmma::fragment<wmma::accumulator, 16, 16, 16, float> c[4];
#pragma unroll
    for (int j = 0; j < 4; j++) wmma::fill_fragment(c[j], 0.f);

    local_stage(tid, &u.s.A[0][0][0], &u.s.B[0][0][0], Asrc, Bsrc, 0, nBase, baseoff);
    for (int it = 0; it < 32; it++) {
        if (it + 1 < 32) {
            int s2 = (it + 1) & 1;
            local_stage(tid, &u.s.A[s2][0][0], &u.s.B[s2][0][0], Asrc, Bsrc, it + 1, nBase, baseoff);
            cp_wait<1>();
        } else {
            cp_wait<0>();
        }
        __syncthreads();
        int s = it & 1;
#pragma unroll
        for (int ks = 0; ks < 32; ks += 16) {
            wmma::fragment<wmma::matrix_a, 16, 16, 16, __half, wmma::row_major> af;
            wmma::load_matrix_sync(af, &u.s.A[s][wm * 16][ks], 40);
#pragma unroll
            for (int j = 0; j < 4; j++) {
                wmma::fragment<wmma::matrix_b, 16, 16, 16, __half, wmma::col_major> bf;
                wmma::load_matrix_sync(bf, &u.s.B[s][wn * 64 + j * 16][ks], 40);
                wmma::mma_sync(c[j], af, bf, c[j]);
            }
        }
        __syncthreads();
    }
#pragma unroll
    for (int j = 0; j < 4; j++)
        wmma::store_matrix_sync(&u.C[(wm * 16) * 136 + wn * 64 + j * 16], c[j], 136,
                                wmma::mem_row_major);
    __syncthreads();
    for (int idx = tid; idx < 76 * 128; idx += 320) {
        int cc = idx >> 7, nn = idx & 127;
        float conf = g_pool[(b * CMn + cc) * 16 + np];
        g_localh[((size_t)bn * 80 + cc) * 512 + nBase + nn] =
            __float2half(u.C[cc * 136 + nn] * conf);
    }
}

// ---------------- 4. k = local @ Wk + bk (WMMA, half out) ----------------
__global__ __launch_bounds__(320, 2) void k_kproj_w(const float* __restrict__ bk) {
    __shared__ __align__(16) union {
        struct { __half A[80][40]; __half B[32][136]; } ab;
        float C[80 * 136];
    } u;
    int bn = blockIdx.y;
    int nBase = blockIdx.x * 128;
    const __half* Ap = g_localh + (size_t)bn * 80 * 512;
    int tid = threadIdx.x;
    int wid = tid >> 5;
    int wm = wid % 5, wn = wid / 5;

    wmma::fragment<wmma::accumulator, 16, 16, 16, float> c[4];
#pragma unroll
    for (int j = 0; j < 4; j++) wmma::fill_fragment(c[j], 0.f);

    for (int k0 = 0; k0 < 512; k0 += 32) {
        {
            int cc = tid >> 2;
            int h8 = (tid & 3) * 8;
            *(uint4*)&u.ab.A[cc][h8] = *(const uint4*)&Ap[(size_t)cc * 512 + k0 + h8];
        }
        for (int idx = tid; idx < 512; idx += 320) {
            int kk = idx >> 4;
            int nn = (idx & 15) * 8;
            *(uint4*)&u.ab.B[kk][nn] = *(const uint4*)&g_Wk_h[(k0 + kk) * MID + nBase + nn];
        }
        __syncthreads();
#pragma unroll
        for (int ks = 0; ks < 32; ks += 16) {
            wmma::fragment<wmma::matrix_a, 16, 16, 16, __half, wmma::row_major> af;
            wmma::load_matrix_sync(af, &u.ab.A[wm * 16][ks], 40);
#pragma unroll
            for (int j = 0; j < 4; j++) {
                wmma::fragment<wmma::matrix_b, 16, 16, 16, __half, wmma::row_major> bf;
                wmma::load_matrix_sync(bf, &u.ab.B[ks][wn * 64 + j * 16], 136);
                wmma::mma_sync(c[j], af, bf, c[j]);
            }
        }
        __syncthreads();
    }
#pragma unroll
    for (int j = 0; j < 4; j++)
        wmma::store_matrix_sync(&u.C[(wm * 16) * 136 + wn * 64 + j * 16], c[j], 136,
                                wmma::mem_row_major);
    __syncthreads();
    for (int idx = tid; idx < 76 * 128; idx += 320) {
        int cc = idx >> 7, nn = idx & 127;
        g_kkh[((size_t)bn * 76 + cc) * 256 + nBase + nn] =
            __float2half(u.C[cc * 136 + nn] + bk[nBase + nn]);
    }
}

// ---------------- 5. W2 = Wq @ K^T per bn, plus b2 = bq @ K^T --------------
// grid (4 mchunks, 64 bn), block 256 (8 warps).
#define W2_SMEM 52480

__global__ __launch_bounds__(256, 2) void k_w2(const float* __restrict__ bq) {
    extern __shared__ __align__(16) char dynw[];
    __half* Ks = (__half*)dynw;                 // [80][264]
    __half* As = (__half*)(dynw + 42240);       // [128][40]
    float* scrb = (float*)(dynw + 42240);       // 8 x [16][20]
    int m0 = blockIdx.x * 128;
    int bn = blockIdx.y;
    int tid = threadIdx.x;
    int lane = tid & 31;
    int wid = tid >> 5;
    const __half* ksrc = g_kkh + (size_t)bn * 76 * 256;

    for (int idx = tid; idx < 2560; idx += 256) {
        int row = idx >> 5, c8 = (idx & 31) * 8;
        uint4 z = {0, 0, 0, 0};
        uint4 val = (row < 76) ? *(const uint4*)&ksrc[(size_t)row * 256 + c8] : z;
        *(uint4*)(Ks + row * 264 + c8) = val;
    }
    __syncthreads();

    if (blockIdx.x == 0 && tid < 80) {
        float s = 0.f;
        for (int mid = 0; mid < 256; mid++) s += bq[mid] * __half2float(Ks[tid * 264 + mid]);
        for (int r = 0; r < 16; r++) g_b2[(size_t)bn * 1280 + r * 80 + tid] = s;
    }

    wmma::fragment<wmma::accumulator, 16, 16, 16, float> acc[5];
#pragma unroll
    for (int f = 0; f < 5; f++) wmma::fill_fragment(acc[f], 0.f);
    for (int k0 = 0; k0 < 256; k0 += 32) {
        __syncthreads();
        for (int idx = tid; idx < 512; idx += 256) {
            int row = idx >> 2, k8 = (idx & 3) * 8;
            *(uint4*)(As + row * 40 + k8) =
                *(const uint4*)&g_Wq_h[(size_t)(m0 + row) * 256 + k0 + k8];
        }
        __syncthreads();
#pragma unroll
        for (int ks = 0; ks < 32; ks += 16) {
            wmma::fragment<wmma::matrix_a, 16, 16, 16, __half, wmma::row_major> af;
            wmma::load_matrix_sync(af, As + (wid * 16) * 40 + ks, 40);
#pragma unroll
            for (int f = 0; f < 5; f++) {
                wmma::fragment<wmma::matrix_b, 16, 16, 16, __half, wmma::col_major> bf;
                wmma::load_matrix_sync(bf, Ks + (f * 16) * 264 + k0 + ks, 264);
                wmma::mma_sync(acc[f], af, bf, acc[f]);
            }
        }
    }
    __syncthreads();
    float* scr = scrb + wid * 320;
#pragma unroll
    for (int f = 0; f < 5; f++) {
        wmma::store_matrix_sync(scr, acc[f], 20, wmma::mem_row_major);
        __syncwarp();
        scr_to_half(scr, g_w2 + ((size_t)bn * 512 + m0 + wid * 16) * 80 + f * 16, 80, lane);
        __syncwarp();
    }
}

// ---------------- 7. fused attention + conv: S, softmax, PV, O@Wc+BN+ReLU --
// grid (16 mtiles, 64 bn), 256 threads (8 warps; 4M x 2N decode).
// dyn smem layout (82 KB):
//   @0      P   [64][88]  half (11264)
//   @11264  O   [64][264] half (33792); Sf [64][92] f32 overlays during S phase
//   @45056  multi-use (36864):
//     S phase:  staging dbuf 2 x { A[32][72]h 4608 + B[32][88]h 5632 } = 20480
//     PV phase: V [80][136]h (21760) + scr 8x[16][20]f @+21760 (10240)
//     C phase:  Wc staging dbuf 2 x [32][136]h (17408); then Cout [128][72]f (36864)
#define ATT3_SMEM 81920

__global__ __launch_bounds__(256) void k_attq(const float* __restrict__ gamma,
                                              const float* __restrict__ beta,
                                              const float* __restrict__ mean,
                                              const float* __restrict__ var,
                                              float* __restrict__ y) {
    extern __shared__ __align__(16) char dyn[];
    __half* P  = (__half*)dyn;                      // [64][88]
    float*  Sf = (float*)(dyn + 11264);             // [64][92]
    __half* Osm = (__half*)(dyn + 11264);           // [64][264]
    int bn = blockIdx.y;
    int b = bn >> 4, np = bn & 15;
    int i0 = (np >> 2) * 32, j0 = (np & 3) * 32;
    int mBase = blockIdx.x * 64;
    int tid = threadIdx.x;
    int lane = tid & 31;
    int wid = tid >> 5;
    int wm = wid & 3;
    int wn = wid >> 2;
    const __half* xb = g_xh + (size_t)b * Cc * HW;
    const __half* w2 = g_w2 + (size_t)bn * 512 * 80;
    int nfr = (wn == 0) ? 3 : 2;
    int nb0 = (wn == 0) ? 0 : 48;

    // ===== phase S: S[64px][80cm] = x^T @ W2 + b2 =====
    {
        wmma::fragment<wmma::accumulator, 16, 16, 16, float> sacc[3];
        for (int f = 0; f < nfr; f++)
            wmma::load_matrix_sync(sacc[f], g_b2 + (size_t)bn * 1280 + nb0 + f * 16, 80,
                                   wmma::mem_row_major);

        auto stage = [&](int s, int k0) {
            char* base = dyn + 45056 + s * 10240;
            for (int idx = tid; idx < 576; idx += 256) {
                if (idx < 256) {
                    int ch = idx >> 3;
                    int px = (idx & 7) * 8;
                    int p = mBase + px;
                    cp16((__half*)base + ch * 72 + px,
                         xb + (size_t)(k0 + ch) * HW + (i0 + (p >> 5)) * 128 + j0 + (p & 31));
                } else {
                    int j = idx - 256;
                    int kk = j / 10;
                    int n = (j % 10) * 8;
                    cp16((__half*)(base + 4608) + kk * 88 + n,
                         w2 + (size_t)(k0 + kk) * 80 + n);
                }
            }
            cp_commit();
        };

        stage(0, 0);
        for (int it = 0; it < 16; it++) {
            if (it + 1 < 16) {
                stage((it + 1) & 1, (it + 1) * 32);
                cp_wait<1>();
            } else {
                cp_wait<0>();
            }
            __syncthreads();
            int s = it & 1;
            __half* As = (__half*)(dyn + 45056 + s * 10240);
            __half* Bs = (__half*)(dyn + 45056 + s * 10240 + 4608);
#pragma unroll
            for (int ks = 0; ks < 32; ks += 16) {
                wmma::fragment<wmma::matrix_a, 16, 16, 16, __half, wmma::col_major> af;
                wmma::load_matrix_sync(af, As + ks * 72 + wm * 16, 72);
                for (int f = 0; f < nfr; f++) {
                    wmma::fragment<wmma::matrix_b, 16, 16, 16, __half, wmma::row_major> bf;
                    wmma::load_matrix_sync(bf, Bs + ks * 88 + nb0 + f * 16, 88);
                    wmma::mma_sync(sacc[f], af, bf, sacc[f]);
                }
            }
            __syncthreads();
        }
        for (int f = 0; f < nfr; f++)
            wmma::store_matrix_sync(Sf + (wm * 16) * 92 + nb0 + f * 16, sacc[f], 92,
                                    wmma::mem_row_major);
    }
    __syncthreads();

    // ===== softmax -> P =====
    if (tid < 64) {
        const float* srow = Sf + tid * 92;
        float mx = -1e30f;
        for (int c = 0; c < 76; c++) mx = fmaxf(mx, srow[c]);
        float s = 0.f;
        float e[76];
        for (int c = 0; c < 76; c++) { e[c] = expf(srow[c] - mx); s += e[c]; }
        float inv = 1.0f / s;
        __half* prow = P + tid * 88;
        for (int c = 0; c < 76; c++) prow[c] = __float2half(e[c] * inv);
        prow[76] = __float2half(0.f);
        prow[77] = __float2half(0.f);
        prow[78] = __float2half(0.f);
        prow[79] = __float2half(0.f);
    }
    __syncthreads();

    // ===== phase PV: O = P @ V -> Osm (half) =====
    {
        __half* Vsm = (__half*)(dyn + 45056);            // [80][136]
        float* scr2 = (float*)(dyn + 45056 + 21760) + wid * 320;
        for (int hb = 0; hb < 2; hb++) {
            for (int idx = tid; idx < 1280; idx += 256) {
                int row = idx >> 4, c8 = (idx & 15) * 8;
                uint4 z = {0, 0, 0, 0};
                uint4 val = (row < 76) ? *(const uint4*)&g_vvh[row * 256 + hb * 128 + c8] : z;
                *(uint4*)(Vsm + row * 136 + c8) = val;
            }
            __syncthreads();
            wmma::fragment<wmma::accumulator, 16, 16, 16, float> oacc[4];
#pragma unroll
            for (int j = 0; j < 4; j++) wmma::fill_fragment(oacc[j], 0.f);
#pragma unroll
            for (int kc = 0; kc < 5; kc++) {
                int ks = kc * 16;
                wmma::fragment<wmma::matrix_a, 16, 16, 16, __half, wmma::row_major> pf;
                wmma::load_matrix_sync(pf, P + (wm * 16) * 88 + ks, 88);
#pragma unroll
                for (int j = 0; j < 4; j++) {
                    wmma::fragment<wmma::matrix_b, 16, 16, 16, __half, wmma::row_major> vf;
                    wmma::load_matrix_sync(vf, Vsm + ks * 136 + wn * 64 + j * 16, 136);
                    wmma::mma_sync(oacc[j], pf, vf, oacc[j]);
                }
            }
            __half* obase = Osm + (wm * 16) * 264 + hb * 128 + wn * 64;
#pragma unroll
            for (int j = 0; j < 4; j++) {
                wmma::store_matrix_sync(scr2, oacc[j], 20, wmma::mem_row_major);
                __syncwarp();
                scr_to_half(scr2, obase + j * 16, 264, lane);
                __syncwarp();
            }
            __syncthreads();
        }
    }

    // ===== phase C: y = ReLU(BN(O @ Wc)), 4 chunks of 128 output channels ==
    for (int nc = 0; nc < 4; nc++) {
        int nb = nc * 128;
        wmma::fragment<wmma::accumulator, 16, 16, 16, float> cacc[4];
#pragma unroll
        for (int j = 0; j < 4; j++) wmma::fill_fragment(cacc[j], 0.f);

        // stage Wc chunk [32k][128ch] (512 uint4 over 256 thr)
        auto stageC = [&](int s, int k0) {
            __half* Bs = (__half*)(dyn + 45056 + s * 8704);
            for (int idx = tid; idx < 512; idx += 256) {
                int kk = idx >> 4, c8 = (idx & 15) * 8;
                cp16(Bs + kk * 136 + c8, g_Wc_h + (size_t)(k0 + kk) * Cc + nb + c8);
            }
            cp_commit();
        };
        stageC(0, 0);
        for (int it = 0; it < 8; it++) {
            if (it + 1 < 8) {
                stageC((it + 1) & 1, (it + 1) * 32);
                cp_wait<1>();
            } else {
                cp_wait<0>();
            }
            __syncthreads();
            int s = it & 1;
            __half* Bs = (__half*)(dyn + 45056 + s * 8704);
            int k0 = it * 32;
#pragma unroll
            for (int ks = 0; ks < 32; ks += 16) {
                wmma::fragment<wmma::matrix_a, 16, 16, 16, __half, wmma::row_major> af;
                wmma::load_matrix_sync(af, Osm + (wm * 16) * 264 + k0 + ks, 264);
#pragma unroll
                for (int j = 0; j < 4; j++) {
                    wmma::fragment<wmma::matrix_b, 16, 16, 16, __half, wmma::row_major> bf;
                    wmma::load_matrix_sync(bf, Bs + ks * 136 + wn * 64 + j * 16, 136);
                    wmma::mma_sync(cacc[j], af, bf, cacc[j]);
                }
            }
            __syncthreads();
        }
        // stage C col-major: Cout[ch][px], ld 72
        float* Cout = (float*)(dyn + 45056);
#pragma unroll
        for (int j = 0; j < 4; j++)
            wmma::store_matrix_sync(Cout + (wn * 64 + j * 16) * 72 + wm * 16, cacc[j], 72,
                                    wmma::mem_col_major);
        __syncthreads();
        // BN + ReLU + write y (128 ch x 64 px; 2 threads per ch)
        {
            int chl = tid >> 1;
            int half = tid & 1;
            int ch = nb + chl;
            float iv = gamma[ch] / sqrtf(var[ch] + 1e-5f);
            float ad = beta[ch] - mean[ch] * iv;
            int px0 = half * 32;
            int p = mBase + px0;
            float* ydst = y + ((size_t)b * Cc + ch) * HW + (i0 + (p >> 5)) * 128 + j0;
            const float* crow = Cout + chl * 72 + px0;
#pragma unroll
            for (int l = 0; l < 8; l++) {
                float4 v = *(const float4*)&crow[l * 4];
                v.x = fmaxf(v.x * iv + ad, 0.f);
                v.y = fmaxf(v.y * iv + ad, 0.f);
                v.z = fmaxf(v.z * iv + ad, 0.f);
                v.w = fmaxf(v.w * iv + ad, 0.f);
                *(float4*)&ydst[l * 4] = v;
            }
        }
        __syncthreads();
    }
}

// ---------------- launcher ----------------
extern "C" void kernel_launch(void* const* d_in, const int* in_sizes, int n_in,
                              void* d_out, int out_size) {
    const float* x   = (const float*)d_in[0];
    const float* sim = (const float*)d_in[1];
    const float* gcc = (const float*)d_in[2];
    const float* Wq  = (const float*)d_in[3];
    const float* bq  = (const float*)d_in[4];
    const float* Wk  = (const float*)d_in[5];
    const float* bk  = (const float*)d_in[6];
    const float* Wv  = (const float*)d_in[7];
    const float* bv  = (const float*)d_in[8];
    const float* Wc  = (const float*)d_in[9];
    const float* gm  = (const float*)d_in[10];
    const float* bt  = (const float*)d_in[11];
    const float* mn  = (const float*)d_in[12];
    const float* vr  = (const float*)d_in[13];
    float* y = (float*)d_out;
    float* tail = y + (size_t)Bsz * Cc * HW;

    cudaFuncSetAttribute(k_w2, cudaFuncAttributeMaxDynamicSharedMemorySize, W2_SMEM);
    cudaFuncSetAttribute(k_attq, cudaFuncAttributeMaxDynamicSharedMemorySize, ATT3_SMEM);

    k_misc<<<7244, 256>>>(x, sim, gcc, Wq, Wk, Wc, Wv, bv, tail);
    k_local_w<<<dim3(4, 64), 320>>>();
    k_kproj_w<<<dim3(2, 64), 320>>>(bk);
    k_w2<<<dim3(4, 64), 256, W2_SMEM>>>(bq);
    k_attq<<<dim3(16, 64), 256, ATT3_SMEM>>>(gm, bt, mn, vr, y);
}

// round 16
// speedup vs baseline: 1.1542x; 1.0498x over previous
#include <cuda_runtime.h>
#include <cuda_fp16.h>
#include <mma.h>
#include <math.h>

using namespace nvcuda;

#define Bsz 4
#define Cc 512
#define MID 256
#define CMn 76
#define Hh 128
#define Ww 128
#define HW 16384
#define Pp 1024
#define Np 16

// ---------------- static scratch ----------------
__device__ float  g_pool[Bsz * CMn * Np];
__device__ __half g_smxh[(size_t)64 * 80 * 1024];       // softmax(sim), padded 80 rows
__device__ __half g_localh[(size_t)64 * 80 * 512];      // local (conf folded), padded
__device__ __half g_kkh[(size_t)64 * 76 * 256];         // k proj (half)
__device__ __half g_vvh[76 * 256];                      // v proj (half)
__device__ __half g_xh[(size_t)Bsz * Cc * HW];          // x as half
__device__ __half g_Wq_h[Cc * MID];
__device__ __half g_Wk_h[Cc * MID];
__device__ __half g_Wc_h[MID * Cc];
__device__ __half g_w2[(size_t)64 * 512 * 80];          // W2 = Wq @ K^T per bn [ch][cm]
__device__ float  g_b2[64 * 16 * 80];                   // b2 = bq @ K^T, replicated 16 rows

// ---------------- cp.async helpers ----------------
__device__ __forceinline__ void cp16(void* dst, const void* src) {
    unsigned d = (unsigned)__cvta_generic_to_shared(dst);
    asm volatile("cp.async.ca.shared.global [%0], [%1], 16;\n" :: "r"(d), "l"(src));
}
__device__ __forceinline__ void cp_commit() { asm volatile("cp.async.commit_group;\n"); }
template <int N>
__device__ __forceinline__ void cp_wait() { asm volatile("cp.async.wait_group %0;\n" :: "n"(N)); }

// convert a 16x16 fp32 warp scratch tile (ld=20) to half and write out (ldg mult of 8).
__device__ __forceinline__ void scr_to_half(const float* scr, __half* gdst, int ldg, int lane) {
    int rr = lane >> 1, c8 = (lane & 1) * 8;
    const float* s = scr + rr * 20 + c8;
    __half2 h0 = __floats2half2_rn(s[0], s[1]);
    __half2 h1 = __floats2half2_rn(s[2], s[3]);
    __half2 h2 = __floats2half2_rn(s[4], s[5]);
    __half2 h3 = __floats2half2_rn(s[6], s[7]);
    uint4 o;
    o.x = *(unsigned*)&h0; o.y = *(unsigned*)&h1;
    o.z = *(unsigned*)&h2; o.w = *(unsigned*)&h3;
    *(uint4*)(gdst + (size_t)rr * ldg + c8) = o;
}

// ---------------- 0. merged misc: setup + x->half + pool/softmax + v -------
__global__ void k_misc(const float* __restrict__ x, const float* __restrict__ sim,
                       const float* __restrict__ gcc,
                       const float* __restrict__ Wq, const float* __restrict__ Wk,
                       const float* __restrict__ Wc,
                       const float* __restrict__ Wv, const float* __restrict__ bv,
                       float* __restrict__ out_tail) {
    __shared__ float red[256];
    __shared__ float sg[512];
    int blk = blockIdx.x;
    int t = threadIdx.x;

    if (blk < 256) {
        int g = blk * 256 + t;
        int stride = 256 * 256;
        for (int i = g; i < Cc * MID; i += stride) {
            g_Wq_h[i] = __float2half(Wq[i]);
            g_Wk_h[i] = __float2half(Wk[i]);
            g_Wc_h[i] = __float2half(Wc[i]);
        }
        for (int i = g; i < 64 * 4 * 1024; i += stride) {
            int bn = i >> 12, rem = i & 4095;
            g_smxh[((size_t)bn * 80 + 76) * 1024 + rem] = __float2half(0.f);
        }
        for (int i = g; i < 64 * 4 * 512; i += stride) {
            int bn = i >> 11, rem = i & 2047;
            g_localh[((size_t)bn * 80 + 76) * 512 + rem] = __float2half(0.f);
        }
    } else if (blk < 2304) {
        size_t n8 = (size_t)Bsz * Cc * HW / 8;
        size_t g = (size_t)(blk - 256) * 256 + t;
        size_t stride = (size_t)2048 * 256;
        for (; g < n8; g += stride) {
            const float4* s = (const float4*)x + g * 2;
            float4 a = s[0], b = s[1];
            __half2 h0 = __floats2half2_rn(a.x, a.y);
            __half2 h1 = __floats2half2_rn(a.z, a.w);
            __half2 h2 = __floats2half2_rn(b.x, b.y);
            __half2 h3 = __floats2half2_rn(b.z, b.w);
            uint4 o;
            o.x = *(unsigned*)&h0; o.y = *(unsigned*)&h1;
            o.z = *(unsigned*)&h2; o.w = *(unsigned*)&h3;
            ((uint4*)g_xh)[g] = o;
        }
    } else if (blk < 7168) {
        int id = blk - 2304;
        int cm = id % CMn;
        int bn = id / CMn;
        int n = bn & 15, b = bn >> 4;
        int i0 = (n >> 2) * 32, j0 = (n & 3) * 32;
        const float* base = sim + ((size_t)b * CMn + cm) * HW;
        float v[4];
        float mx = -1e30f, sraw = 0.f;
#pragma unroll
        for (int it = 0; it < 4; it++) {
            int p = t + it * 256;
            int pi = p >> 5, pj = p & 31;
            v[it] = base[(i0 + pi) * Ww + j0 + pj];
            mx = fmaxf(mx, v[it]);
            sraw += v[it];
        }
        red[t] = sraw; __syncthreads();
        for (int o = 128; o > 0; o >>= 1) {
            if (t < o) red[t] += red[t + o];
            __syncthreads();
        }
        if (t == 0) {
            float m = red[0] * (1.0f / 1024.0f);
            int pid = (b * CMn + cm) * 16 + n;
            g_pool[pid] = m;
            out_tail[pid] = m;
        }
        __syncthreads();
        red[t] = mx; __syncthreads();
        for (int o = 128; o > 0; o >>= 1) {
            if (t < o) red[t] = fmaxf(red[t], red[t + o]);
            __syncthreads();
        }
        float gmx = red[0]; __syncthreads();
        float s = 0.f;
#pragma unroll
        for (int it = 0; it < 4; it++) { v[it] = expf(v[it] - gmx); s += v[it]; }
        red[t] = s; __syncthreads();
        for (int o = 128; o > 0; o >>= 1) {
            if (t < o) red[t] += red[t + o];
            __syncthreads();
        }
        float inv = 1.0f / red[0];
        __half* dst = g_smxh + ((size_t)bn * 80 + cm) * Pp;
#pragma unroll
        for (int it = 0; it < 4; it++) { int p = t + it * 256; dst[p] = __float2half(v[it] * inv); }
    } else {
        int c = blk - 7168;
        for (int k = t; k < 512; k += 256) sg[k] = gcc[c * 512 + k];
        __syncthreads();
        float acc = 0.f;
        for (int k = 0; k < 512; k++) acc += sg[k] * Wv[k * MID + t];
        g_vvh[c * MID + t] = __float2half(acc + bv[t]);
    }
}

// ---------------- 3. local = smx^T @ xs * conf  (WMMA, cp.async x2) --------
__device__ __forceinline__ void local_stage(int tid, __half* Adst, __half* Bdst,
                                            const __half* Asrc, const __half* Bsrc,
                                            int it, int nBase, int baseoff) {
    for (int idx = tid; idx < 832; idx += 320) {
        if (idx < 320) {
            int row = idx >> 2, col = (idx & 3) * 8;
            cp16(Adst + row * 40 + col, Asrc + (size_t)row * 1024 + it * 32 + col);
        } else {
            int j = idx - 320;
            int row = j >> 2, col = (j & 3) * 8;
            cp16(Bdst + row * 40 + col,
                 Bsrc + (size_t)(nBase + row) * HW + baseoff + it * Ww + col);
        }
    }
    cp_commit();
}

__global__ __launch_bounds__(320, 2) void k_local_w() {
    __shared__ __align__(16) union {
        struct { __half A[2][80][40]; __half B[2][128][40]; } s;
        float C[80 * 136];
    } u;
    int bn = blockIdx.y;
    int b = bn >> 4, np = bn & 15;
    int i0 = (np >> 2) * 32, j0 = (np & 3) * 32;
    int baseoff = i0 * Ww + j0;
    int nBase = blockIdx.x * 128;
    const __half* Asrc = g_smxh + (size_t)bn * 80 * 1024;
    const __half* Bsrc = g_xh + (size_t)b * Cc * HW;
    int tid = threadIdx.x;
    int wid = tid >> 5;
    int wm = wid % 5, wn = wid / 5;

    wmma::fragment<wmma::accumulator, 16, 16, 16, float> c[4];
#pragma unroll
    for (int j = 0; j < 4; j++) wmma::fill_fragment(c[j], 0.f);

    local_stage(tid, &u.s.A[0][0][0], &u.s.B[0][0][0], Asrc, Bsrc, 0, nBase, baseoff);
    for (int it = 0; it < 32; it++) {
        if (it + 1 < 32) {
            int s2 = (it + 1) & 1;
            local_stage(tid, &u.s.A[s2][0][0], &u.s.B[s2][0][0], Asrc, Bsrc, it + 1, nBase, baseoff);
            cp_wait<1>();
        } else {
            cp_wait<0>();
        }
        __syncthreads();
        int s = it & 1;
#pragma unroll
        for (int ks = 0; ks < 32; ks += 16) {
            wmma::fragment<wmma::matrix_a, 16, 16, 16, __half, wmma::row_major> af;
            wmma::load_matrix_sync(af, &u.s.A[s][wm * 16][ks], 40);
#pragma unroll
            for (int j = 0; j < 4; j++) {
                wmma::fragment<wmma::matrix_b, 16, 16, 16, __half, wmma::col_major> bf;
                wmma::load_matrix_sync(bf, &u.s.B[s][wn * 64 + j * 16][ks], 40);
                wmma::mma_sync(c[j], af, bf, c[j]);
            }
        }
        __syncthreads();
    }
#pragma unroll
    for (int j = 0; j < 4; j++)
        wmma::store_matrix_sync(&u.C[(wm * 16) * 136 + wn * 64 + j * 16], c[j], 136,
                                wmma::mem_row_major);
    __syncthreads();
    for (int idx = tid; idx < 76 * 128; idx += 320) {
        int cc = idx >> 7, nn = idx & 127;
        float conf = g_pool[(b * CMn + cc) * 16 + np];
        g_localh[((size_t)bn * 80 + cc) * 512 + nBase + nn] =
            __float2half(u.C[cc * 136 + nn] * conf);
    }
}

// ---------------- 4. k = local @ Wk + bk (WMMA, half out, K-chunk 64) ------
__global__ __launch_bounds__(320, 2) void k_kproj_w(const float* __restrict__ bk) {
    __shared__ __align__(16) union {
        struct { __half A[80][72]; __half B[64][136]; } ab;
        float C[80 * 136];
    } u;
    int bn = blockIdx.y;
    int nBase = blockIdx.x * 128;
    const __half* Ap = g_localh + (size_t)bn * 80 * 512;
    int tid = threadIdx.x;
    int wid = tid >> 5;
    int wm = wid % 5, wn = wid / 5;

    wmma::fragment<wmma::accumulator, 16, 16, 16, float> c[4];
#pragma unroll
    for (int j = 0; j < 4; j++) wmma::fill_fragment(c[j], 0.f);

    for (int k0 = 0; k0 < 512; k0 += 64) {
        // A: 80 rows x 64 half (640 uint4); B: 64 rows x 128 half (1024 uint4)
        for (int idx = tid; idx < 1664; idx += 320) {
            if (idx < 640) {
                int cc = idx >> 3;
                int h8 = (idx & 7) * 8;
                *(uint4*)&u.ab.A[cc][h8] = *(const uint4*)&Ap[(size_t)cc * 512 + k0 + h8];
            } else {
                int j = idx - 640;
                int kk = j >> 4;
                int nn = (j & 15) * 8;
                *(uint4*)&u.ab.B[kk][nn] = *(const uint4*)&g_Wk_h[(k0 + kk) * MID + nBase + nn];
            }
        }
        __syncthreads();
#pragma unroll
        for (int ks = 0; ks < 64; ks += 16) {
            wmma::fragment<wmma::matrix_a, 16, 16, 16, __half, wmma::row_major> af;
            wmma::load_matrix_sync(af, &u.ab.A[wm * 16][ks], 72);
#pragma unroll
            for (int j = 0; j < 4; j++) {
                wmma::fragment<wmma::matrix_b, 16, 16, 16, __half, wmma::row_major> bf;
                wmma::load_matrix_sync(bf, &u.ab.B[ks][wn * 64 + j * 16], 136);
                wmma::mma_sync(c[j], af, bf, c[j]);
            }
        }
        __syncthreads();
    }
#pragma unroll
    for (int j = 0; j < 4; j++)
        wmma::store_matrix_sync(&u.C[(wm * 16) * 136 + wn * 64 + j * 16], c[j], 136,
                                wmma::mem_row_major);
    __syncthreads();
    for (int idx = tid; idx < 76 * 128; idx += 320) {
        int cc = idx >> 7, nn = idx & 127;
        g_kkh[((size_t)bn * 76 + cc) * 256 + nBase + nn] =
            __float2half(u.C[cc * 136 + nn] + bk[nBase + nn]);
    }
}

// ---------------- 5. W2 = Wq @ K^T per bn, plus b2 = bq @ K^T --------------
// grid (4 mchunks, 64 bn), block 256 (8 warps).
#define W2_SMEM 52480

__global__ __launch_bounds__(256, 2) void k_w2(const float* __restrict__ bq) {
    extern __shared__ __align__(16) char dynw[];
    __half* Ks = (__half*)dynw;                 // [80][264]
    __half* As = (__half*)(dynw + 42240);       // [128][40]
    float* scrb = (float*)(dynw + 42240);       // 8 x [16][20]
    int m0 = blockIdx.x * 128;
    int bn = blockIdx.y;
    int tid = threadIdx.x;
    int lane = tid & 31;
    int wid = tid >> 5;
    const __half* ksrc = g_kkh + (size_t)bn * 76 * 256;

    for (int idx = tid; idx < 2560; idx += 256) {
        int row = idx >> 5, c8 = (idx & 31) * 8;
        uint4 z = {0, 0, 0, 0};
        uint4 val = (row < 76) ? *(const uint4*)&ksrc[(size_t)row * 256 + c8] : z;
        *(uint4*)(Ks + row * 264 + c8) = val;
    }
    __syncthreads();

    if (blockIdx.x == 0 && tid < 80) {
        float s = 0.f;
        for (int mid = 0; mid < 256; mid++) s += bq[mid] * __half2float(Ks[tid * 264 + mid]);
        for (int r = 0; r < 16; r++) g_b2[(size_t)bn * 1280 + r * 80 + tid] = s;
    }

    wmma::fragment<wmma::accumulator, 16, 16, 16, float> acc[5];
#pragma unroll
    for (int f = 0; f < 5; f++) wmma::fill_fragment(acc[f], 0.f);
    for (int k0 = 0; k0 < 256; k0 += 32) {
        __syncthreads();
        for (int idx = tid; idx < 512; idx += 256) {
            int row = idx >> 2, k8 = (idx & 3) * 8;
            *(uint4*)(As + row * 40 + k8) =
                *(const uint4*)&g_Wq_h[(size_t)(m0 + row) * 256 + k0 + k8];
        }
        __syncthreads();
#pragma unroll
        for (int ks = 0; ks < 32; ks += 16) {
            wmma::fragment<wmma::matrix_a, 16, 16, 16, __half, wmma::row_major> af;
            wmma::load_matrix_sync(af, As + (wid * 16) * 40 + ks, 40);
#pragma unroll
            for (int f = 0; f < 5; f++) {
                wmma::fragment<wmma::matrix_b, 16, 16, 16, __half, wmma::col_major> bf;
                wmma::load_matrix_sync(bf, Ks + (f * 16) * 264 + k0 + ks, 264);
                wmma::mma_sync(acc[f], af, bf, acc[f]);
            }
        }
    }
    __syncthreads();
    float* scr = scrb + wid * 320;
#pragma unroll
    for (int f = 0; f < 5; f++) {
        wmma::store_matrix_sync(scr, acc[f], 20, wmma::mem_row_major);
        __syncwarp();
        scr_to_half(scr, g_w2 + ((size_t)bn * 512 + m0 + wid * 16) * 80 + f * 16, 80, lane);
        __syncwarp();
    }
}

// ---------------- 7. fused attention + conv: S, softmax, PV, O@Wc+BN+ReLU --
// grid (16 mtiles, 64 bn), 256 threads (8 warps; 4M x 2N decode).
// dyn smem layout (82 KB):
//   @0      P   [64][88]  half (11264)
//   @11264  O   [64][264] half (33792); Sf [64][92] f32 overlays during S phase
//   @45056  multi-use (36864):
//     S phase:  staging dbuf 2 x { A[32][72]h 4608 + B[32][88]h 5632 } = 20480
//     PV phase: V [80][136]h (21760) + scr 8x[16][20]f @+21760 (10240)
//     C phase:  Wc staging dbuf 2 x [64][136]h (34816); then Cout [128][72]f (36864)
#define ATT3_SMEM 81920

__global__ __launch_bounds__(256) void k_attq(const float* __restrict__ gamma,
                                              const float* __restrict__ beta,
                                              const float* __restrict__ mean,
                                              const float* __restrict__ var,
                                              float* __restrict__ y) {
    extern __shared__ __align__(16) char dyn[];
    __half* P  = (__half*)dyn;                      // [64][88]
    float*  Sf = (float*)(dyn + 11264);             // [64][92]
    __half* Osm = (__half*)(dyn + 11264);           // [64][264]
    int bn = blockIdx.y;
    int b = bn >> 4, np = bn & 15;
    int i0 = (np >> 2) * 32, j0 = (np & 3) * 32;
    int mBase = blockIdx.x * 64;
    int tid = threadIdx.x;
    int lane = tid & 31;
    int wid = tid >> 5;
    int wm = wid & 3;
    int wn = wid >> 2;
    const __half* xb = g_xh + (size_t)b * Cc * HW;
    const __half* w2 = g_w2 + (size_t)bn * 512 * 80;
    int nfr = (wn == 0) ? 3 : 2;
    int nb0 = (wn == 0) ? 0 : 48;

    // ===== phase S: S[64px][80cm] = x^T @ W2 + b2 =====
    {
        wmma::fragment<wmma::accumulator, 16, 16, 16, float> sacc[3];
        for (int f = 0; f < nfr; f++)
            wmma::load_matrix_sync(sacc[f], g_b2 + (size_t)bn * 1280 + nb0 + f * 16, 80,
                                   wmma::mem_row_major);

        auto stage = [&](int s, int k0) {
            char* base = dyn + 45056 + s * 10240;
            for (int idx = tid; idx < 576; idx += 256) {
                if (idx < 256) {
                    int ch = idx >> 3;
                    int px = (idx & 7) * 8;
                    int p = mBase + px;
                    cp16((__half*)base + ch * 72 + px,
                         xb + (size_t)(k0 + ch) * HW + (i0 + (p >> 5)) * 128 + j0 + (p & 31));
                } else {
                    int j = idx - 256;
                    int kk = j / 10;
                    int n = (j % 10) * 8;
                    cp16((__half*)(base + 4608) + kk * 88 + n,
                         w2 + (size_t)(k0 + kk) * 80 + n);
                }
            }
            cp_commit();
        };

        stage(0, 0);
        for (int it = 0; it < 16; it++) {
            if (it + 1 < 16) {
                stage((it + 1) & 1, (it + 1) * 32);
                cp_wait<1>();
            } else {
                cp_wait<0>();
            }
            __syncthreads();
            int s = it & 1;
            __half* As = (__half*)(dyn + 45056 + s * 10240);
            __half* Bs = (__half*)(dyn + 45056 + s * 10240 + 4608);
#pragma unroll
            for (int ks = 0; ks < 32; ks += 16) {
                wmma::fragment<wmma::matrix_a, 16, 16, 16, __half, wmma::col_major> af;
                wmma::load_matrix_sync(af, As + ks * 72 + wm * 16, 72);
                for (int f = 0; f < nfr; f++) {
                    wmma::fragment<wmma::matrix_b, 16, 16, 16, __half, wmma::row_major> bf;
                    wmma::load_matrix_sync(bf, Bs + ks * 88 + nb0 + f * 16, 88);
                    wmma::mma_sync(sacc[f], af, bf, sacc[f]);
                }
            }
            __syncthreads();
        }
        for (int f = 0; f < nfr; f++)
            wmma::store_matrix_sync(Sf + (wm * 16) * 92 + nb0 + f * 16, sacc[f], 92,
                                    wmma::mem_row_major);
    }
    __syncthreads();

    // ===== softmax -> P =====
    if (tid < 64) {
        const float* srow = Sf + tid * 92;
        float mx = -1e30f;
        for (int c = 0; c < 76; c++) mx = fmaxf(mx, srow[c]);
        float s = 0.f;
        float e[76];
        for (int c = 0; c < 76; c++) { e[c] = expf(srow[c] - mx); s += e[c]; }
        float inv = 1.0f / s;
        __half* prow = P + tid * 88;
        for (int c = 0; c < 76; c++) prow[c] = __float2half(e[c] * inv);
        prow[76] = __float2half(0.f);
        prow[77] = __float2half(0.f);
        prow[78] = __float2half(0.f);
        prow[79] = __float2half(0.f);
    }
    __syncthreads();

    // ===== phase PV: O = P @ V -> Osm (half) =====
    {
        __half* Vsm = (__half*)(dyn + 45056);            // [80][136]
        float* scr2 = (float*)(dyn + 45056 + 21760) + wid * 320;
        for (int hb = 0; hb < 2; hb++) {
            for (int idx = tid; idx < 1280; idx += 256) {
                int row = idx >> 4, c8 = (idx & 15) * 8;
                uint4 z = {0, 0, 0, 0};
                uint4 val = (row < 76) ? *(const uint4*)&g_vvh[row * 256 + hb * 128 + c8] : z;
                *(uint4*)(Vsm + row * 136 + c8) = val;
            }
            __syncthreads();
            wmma::fragment<wmma::accumulator, 16, 16, 16, float> oacc[4];
#pragma unroll
            for (int j = 0; j < 4; j++) wmma::fill_fragment(oacc[j], 0.f);
#pragma unroll
            for (int kc = 0; kc < 5; kc++) {
                int ks = kc * 16;
                wmma::fragment<wmma::matrix_a, 16, 16, 16, __half, wmma::row_major> pf;
                wmma::load_matrix_sync(pf, P + (wm * 16) * 88 + ks, 88);
#pragma unroll
                for (int j = 0; j < 4; j++) {
                    wmma::fragment<wmma::matrix_b, 16, 16, 16, __half, wmma::row_major> vf;
                    wmma::load_matrix_sync(vf, Vsm + ks * 136 + wn * 64 + j * 16, 136);
                    wmma::mma_sync(oacc[j], pf, vf, oacc[j]);
                }
            }
            __half* obase = Osm + (wm * 16) * 264 + hb * 128 + wn * 64;
#pragma unroll
            for (int j = 0; j < 4; j++) {
                wmma::store_matrix_sync(scr2, oacc[j], 20, wmma::mem_row_major);
                __syncwarp();
                scr_to_half(scr2, obase + j * 16, 264, lane);
                __syncwarp();
            }
            __syncthreads();
        }
    }

    // ===== phase C: y = ReLU(BN(O @ Wc)), 4 chunks x 128 out ch, K-chunk 64 =
    for (int nc = 0; nc < 4; nc++) {
        int nb = nc * 128;
        wmma::fragment<wmma::accumulator, 16, 16, 16, float> cacc[4];
#pragma unroll
        for (int j = 0; j < 4; j++) wmma::fill_fragment(cacc[j], 0.f);

        // stage Wc chunk [64k][128ch] (1024 cp16 over 256 thr = 4 each)
        auto stageC = [&](int s, int k0) {
            __half* Bs = (__half*)(dyn + 45056 + s * 17408);
#pragma unroll
            for (int l = 0; l < 4; l++) {
                int idx = tid + l * 256;
                int kk = idx >> 4, c8 = (idx & 15) * 8;
                cp16(Bs + kk * 136 + c8, g_Wc_h + (size_t)(k0 + kk) * Cc + nb + c8);
            }
            cp_commit();
        };
        stageC(0, 0);
        for (int it = 0; it < 4; it++) {
            if (it + 1 < 4) {
                stageC((it + 1) & 1, (it + 1) * 64);
                cp_wait<1>();
            } else {
                cp_wait<0>();
            }
            __syncthreads();
            int s = it & 1;
            __half* Bs = (__half*)(dyn + 45056 + s * 17408);
            int k0 = it * 64;
#pragma unroll
            for (int ks = 0; ks < 64; ks += 16) {
                wmma::fragment<wmma::matrix_a, 16, 16, 16, __half, wmma::row_major> af;
                wmma::load_matrix_sync(af, Osm + (wm * 16) * 264 + k0 + ks, 264);
#pragma unroll
                for (int j = 0; j < 4; j++) {
                    wmma::fragment<wmma::matrix_b, 16, 16, 16, __half, wmma::row_major> bf;
                    wmma::load_matrix_sync(bf, Bs + ks * 136 + wn * 64 + j * 16, 136);
                    wmma::mma_sync(cacc[j], af, bf, cacc[j]);
                }
            }
            __syncthreads();
        }
        // stage C col-major: Cout[ch][px], ld 72
        float* Cout = (float*)(dyn + 45056);
#pragma unroll
        for (int j = 0; j < 4; j++)
            wmma::store_matrix_sync(Cout + (wn * 64 + j * 16) * 72 + wm * 16, cacc[j], 72,
                                    wmma::mem_col_major);
        __syncthreads();
        // BN + ReLU + write y (128 ch x 64 px; 2 threads per ch)
        {
            int chl = tid >> 1;
            int half = tid & 1;
            int ch = nb + chl;
            float iv = gamma[ch] / sqrtf(var[ch] + 1e-5f);
            float ad = beta[ch] - mean[ch] * iv;
            int px0 = half * 32;
            int p = mBase + px0;
            float* ydst = y + ((size_t)b * Cc + ch) * HW + (i0 + (p >> 5)) * 128 + j0;
            const float* crow = Cout + chl * 72 + px0;
#pragma unroll
            for (int l = 0; l < 8; l++) {
                float4 v = *(const float4*)&crow[l * 4];
                v.x = fmaxf(v.x * iv + ad, 0.f);
                v.y = fmaxf(v.y * iv + ad, 0.f);
                v.z = fmaxf(v.z * iv + ad, 0.f);
                v.w = fmaxf(v.w * iv + ad, 0.f);
                *(float4*)&ydst[l * 4] = v;
            }
        }
        __syncthreads();
    }
}

// ---------------- launcher ----------------
extern "C" void kernel_launch(void* const* d_in, const int* in_sizes, int n_in,
                              void* d_out, int out_size) {
    const float* x   = (const float*)d_in[0];
    const float* sim = (const float*)d_in[1];
    const float* gcc = (const float*)d_in[2];
    const float* Wq  = (const float*)d_in[3];
    const float* bq  = (const float*)d_in[4];
    const float* Wk  = (const float*)d_in[5];
    const float* bk  = (const float*)d_in[6];
    const float* Wv  = (const float*)d_in[7];
    const float* bv  = (const float*)d_in[8];
    const float* Wc  = (const float*)d_in[9];
    const float* gm  = (const float*)d_in[10];
    const float* bt  = (const float*)d_in[11];
    const float* mn  = (const float*)d_in[12];
    const float* vr  = (const float*)d_in[13];
    float* y = (float*)d_out;
    float* tail = y + (size_t)Bsz * Cc * HW;

    cudaFuncSetAttribute(k_w2, cudaFuncAttributeMaxDynamicSharedMemorySize, W2_SMEM);
    cudaFuncSetAttribute(k_attq, cudaFuncAttributeMaxDynamicSharedMemorySize, ATT3_SMEM);

    k_misc<<<7244, 256>>>(x, sim, gcc, Wq, Wk, Wc, Wv, bv, tail);
    k_local_w<<<dim3(4, 64), 320>>>();
    k_kproj_w<<<dim3(2, 64), 320>>>(bk);
    k_w2<<<dim3(4, 64), 256, W2_SMEM>>>(bq);
    k_attq<<<dim3(16, 64), 256, ATT3_SMEM>>>(gm, bt, mn, vr, y);
}